// round 9
// baseline (speedup 1.0000x reference)
#include <cuda_runtime.h>
#include <cuda_bf16.h>
#include <stdint.h>

// ---------------------------------------------------------------------------
// HeteroGraphSAGE, 2 layers, 4 node types, 8 relations.
// agg[d] = Wr * (inv[d] * sum_e w_e * x[src]) -> CSR gather (no atomics),
// aggr + x0 pre-split bf16 (hi+lo, fp32-accurate ~2^-16); hidden h kept fp32.
// One K-concat mma.sync GEMM per dst type, LDG/STS fills, occupancy 2.
// ---------------------------------------------------------------------------

#define NU 200000
#define NP 100000
#define NC 2000
#define NQ 50000
#define NTOT 352000
#define HID 128

#define NROWS 802000
#define ETOT  2400000
#define NWCHUNK 24

#define LDS 72              // bf16 per smem row (64 data + 8 pad -> 144B pitch)
#define LDSB 144
#define TILE_B (128 * LDSB)          // 18432 B per 128x64 bf16 tile
#define GSMEM (4 * TILE_B)           // Ah, Al, Wh, Wl = 73728 B (occ 2)

// device globals (allocation-free scratch)
__device__ __nv_bfloat16 g_ahi[(size_t)NROWS * HID];
__device__ __nv_bfloat16 g_alo[(size_t)NROWS * HID];
__device__ __nv_bfloat16 g_xhi[(size_t)NTOT * HID];   // x0 pre-split
__device__ __nv_bfloat16 g_xlo[(size_t)NTOT * HID];
__device__ float g_h[(size_t)NTOT * HID];             // hidden after layer 1 (fp32)
__device__ int   g_cnt[NROWS];
__device__ int   g_rowptr[NROWS + 1];
__device__ int   g_cursor[NROWS];
__device__ int   g_srcg[ETOT];
__device__ float g_wg[ETOT];
__device__ int   g_bsums[512];
__device__ float g_wsum[2 * 4 * HID * HID];
__device__ float g_bsum[2 * 4 * HID];
__device__ __nv_bfloat16 g_wh[NWCHUNK * HID * HID];
__device__ __nv_bfloat16 g_wl[NWCHUNK * HID * HID];

// ---------------------------------------------------------------------------
// PTX helpers
// ---------------------------------------------------------------------------
#define LDSM4(R, addr)                                                          \
    asm volatile("ldmatrix.sync.aligned.m8n8.x4.shared.b16 {%0,%1,%2,%3}, [%4];" \
                 : "=r"((R)[0]), "=r"((R)[1]), "=r"((R)[2]), "=r"((R)[3])        \
                 : "r"(addr))

#define MMA16816(C, A, B0, B1)                                                  \
    asm volatile("mma.sync.aligned.m16n8k16.row.col.f32.bf16.bf16.f32 "         \
                 "{%0,%1,%2,%3},{%4,%5,%6,%7},{%8,%9},{%0,%1,%2,%3};"           \
                 : "+f"((C)[0]), "+f"((C)[1]), "+f"((C)[2]), "+f"((C)[3])        \
                 : "r"((A)[0]), "r"((A)[1]), "r"((A)[2]), "r"((A)[3]),           \
                   "r"(B0), "r"(B1))

__device__ __forceinline__ uint32_t pack_bf16(__nv_bfloat16 a, __nv_bfloat16 b)
{
    __nv_bfloat162 p = __halves2bfloat162(a, b);
    return *reinterpret_cast<uint32_t*>(&p);
}

__device__ __forceinline__ void split_pair(float x, float y, uint32_t& hi, uint32_t& lo)
{
    __nv_bfloat16 hx = __float2bfloat16(x);
    __nv_bfloat16 hy = __float2bfloat16(y);
    __nv_bfloat16 lx = __float2bfloat16(x - __bfloat162float(hx));
    __nv_bfloat16 ly = __float2bfloat16(y - __bfloat162float(hy));
    hi = pack_bf16(hx, hy);
    lo = pack_bf16(lx, ly);
}

// ---------------------------------------------------------------------------
// Multi-chunk tensor-core GEMM (bf16x3 split), LDG/STS fills, occupancy 2:
//   C = bias + sum_ch A_ch @ W_ch^T   (each chunk K=128 as 2 halves of K=64)
// Chunk 0: either fp32 A0f (convert in-kernel) or pre-split A0h/A0l (copy).
// Chunks 1..3 + all W: pre-split bf16 (copy). 8 warps (4m x 2n).
// ---------------------------------------------------------------------------
struct GemmArgs {
    const float* A0f;
    const __nv_bfloat16 *A0h, *A0l, *A1h, *A1l, *A2h, *A2l, *A3h, *A3l;
    const __nv_bfloat16 *W0h, *W0l, *W1h, *W1l, *W2h, *W2l, *W3h, *W3l;
};

__global__ void __launch_bounds__(256, 2)
gemm_mma(GemmArgs p, int nch, int a0split, const float* __restrict__ bias,
         float* __restrict__ C, int n, int dorelu)
{
    extern __shared__ __nv_bfloat16 smem[];
    uint32_t sb = (uint32_t)__cvta_generic_to_shared(smem);

    const int tid  = threadIdx.x;
    const int lane = tid & 31;
    const int warp = tid >> 5;
    const int wm = warp >> 1;
    const int wn = warp & 1;
    const int bm = blockIdx.x * 128;

    float c[2][8][4];
#pragma unroll
    for (int i = 0; i < 2; i++)
#pragma unroll
        for (int j = 0; j < 8; j++)
#pragma unroll
            for (int q = 0; q < 4; q++) c[i][j][q] = 0.f;

#pragma unroll
    for (int ch = 0; ch < 4; ch++) {
        if (ch < nch) {
            const __nv_bfloat16* Wh = (ch == 0) ? p.W0h : (ch == 1) ? p.W1h
                                    : (ch == 2) ? p.W2h : p.W3h;
            const __nv_bfloat16* Wl = (ch == 0) ? p.W0l : (ch == 1) ? p.W1l
                                    : (ch == 2) ? p.W2l : p.W3l;
            const __nv_bfloat16* Ahi = (ch == 0) ? p.A0h : (ch == 1) ? p.A1h
                                     : (ch == 2) ? p.A2h : p.A3h;
            const __nv_bfloat16* Alo = (ch == 0) ? p.A0l : (ch == 1) ? p.A1l
                                     : (ch == 2) ? p.A2l : p.A3l;

            for (int kb = 0; kb < 128; kb += 64) {
                // ---- A fill ----
                if (ch == 0 && !a0split) {
                    // fp32 -> split-bf16 conversion path
#pragma unroll
                    for (int it = 0; it < 8; it++) {
                        int idx = tid + it * 256;
                        int r   = idx >> 4;
                        int kc  = (idx & 15) << 2;
                        float4 va = make_float4(0.f, 0.f, 0.f, 0.f);
                        int row = bm + r;
                        if (row < n)
                            va = *(const float4*)(p.A0f + (size_t)row * HID + kb + kc);
                        uint32_t h01, l01, h23, l23;
                        split_pair(va.x, va.y, h01, l01);
                        split_pair(va.z, va.w, h23, l23);
                        size_t so = (size_t)r * LDS + kc;
                        *(uint2*)(smem + so)          = make_uint2(h01, h23);
                        *(uint2*)(smem + 128 * LDS + so) = make_uint2(l01, l23);
                    }
                } else {
                    // direct copy of pre-split bf16 (16B per load)
                    const uint4 z = make_uint4(0, 0, 0, 0);
#pragma unroll
                    for (int it = 0; it < 4; it++) {
                        int idx = tid + it * 256;          // 0..1023
                        int r   = idx >> 3;
                        int kc  = (idx & 7) << 3;
                        int row = bm + r;
                        size_t go = (size_t)row * HID + kb + kc;
                        size_t so = (size_t)r * LDS + kc;
                        uint4 vh = (row < n) ? *(const uint4*)(Ahi + go) : z;
                        uint4 vl = (row < n) ? *(const uint4*)(Alo + go) : z;
                        *(uint4*)(smem + so)             = vh;
                        *(uint4*)(smem + 128 * LDS + so) = vl;
                    }
                }
                // ---- W fill (pre-split, direct copy) ----
#pragma unroll
                for (int it = 0; it < 4; it++) {
                    int idx = tid + it * 256;
                    int r   = idx >> 3;
                    int kc  = (idx & 7) << 3;
                    size_t go = (size_t)r * HID + kb + kc;
                    size_t so = (size_t)r * LDS + kc;
                    *(uint4*)(smem + 2 * 128 * LDS + so) = *(const uint4*)(Wh + go);
                    *(uint4*)(smem + 3 * 128 * LDS + so) = *(const uint4*)(Wl + go);
                }
                __syncthreads();

                // ---- 4 k-steps of 16 ----
#pragma unroll
                for (int ks = 0; ks < 4; ks++) {
                    uint32_t ah[2][4], al[2][4], bh[4][4], bl[4][4];
#pragma unroll
                    for (int i = 0; i < 2; i++) {
                        int r   = wm * 32 + i * 16 + (lane & 15);
                        int kby = ks * 32 + ((lane >> 4) << 4);
                        uint32_t ad = sb + r * LDSB + kby;
                        LDSM4(ah[i], ad);
                        LDSM4(al[i], ad + TILE_B);
                    }
#pragma unroll
                    for (int pq = 0; pq < 4; pq++) {
                        int nr  = wn * 64 + (2 * pq + (lane >> 4)) * 8 + (lane & 7);
                        int kby = ks * 32 + ((lane >> 3) & 1) * 16;
                        uint32_t ad = sb + 2 * TILE_B + nr * LDSB + kby;
                        LDSM4(bh[pq], ad);
                        LDSM4(bl[pq], ad + TILE_B);
                    }
#pragma unroll
                    for (int i = 0; i < 2; i++)
#pragma unroll
                        for (int j = 0; j < 8; j++) {
                            const uint32_t* b = bh[j >> 1] + (j & 1) * 2;
                            MMA16816(c[i][j], ah[i], b[0], b[1]);
                        }
#pragma unroll
                    for (int i = 0; i < 2; i++)
#pragma unroll
                        for (int j = 0; j < 8; j++) {
                            const uint32_t* b = bl[j >> 1] + (j & 1) * 2;
                            MMA16816(c[i][j], ah[i], b[0], b[1]);
                        }
#pragma unroll
                    for (int i = 0; i < 2; i++)
#pragma unroll
                        for (int j = 0; j < 8; j++) {
                            const uint32_t* b = bh[j >> 1] + (j & 1) * 2;
                            MMA16816(c[i][j], al[i], b[0], b[1]);
                        }
                }
                __syncthreads();
            }
        }
    }

    // ---- epilogue ----
    const int g  = lane >> 2;
    const int tq = lane & 3;
#pragma unroll
    for (int i = 0; i < 2; i++) {
#pragma unroll
        for (int half = 0; half < 2; half++) {
            int row = bm + wm * 32 + i * 16 + half * 8 + g;
            if (row >= n) continue;
#pragma unroll
            for (int j = 0; j < 8; j++) {
                int col = wn * 64 + j * 8 + tq * 2;
                float vx = c[i][j][half * 2 + 0] + bias[col];
                float vy = c[i][j][half * 2 + 1] + bias[col + 1];
                if (dorelu) {
                    vx = fmaxf(vx, 0.f);
                    vy = fmaxf(vy, 0.f);
                }
                *(float2*)(C + (size_t)row * HID + col) = make_float2(vx, vy);
            }
        }
    }
}

// ---------------------------------------------------------------------------
// merged CSR count over all 8 relations
// ---------------------------------------------------------------------------
__global__ void csr_count(const int* __restrict__ eb, const int* __restrict__ es,
                          const int* __restrict__ em, const int* __restrict__ ein,
                          int* __restrict__ cnt)
{
    int e = blockIdx.x * 256 + threadIdx.x;
    if (e >= ETOT) return;
    const int* dstp; int rowOff, le;
    if      (e <  500000) { dstp = eb + 500000;  rowOff = 0;      le = e; }
    else if (e < 1000000) { dstp = eb;           rowOff = 100000; le = e - 500000; }
    else if (e < 1300000) { dstp = es + 300000;  rowOff = 300000; le = e - 1000000; }
    else if (e < 1600000) { dstp = es;           rowOff = 350000; le = e - 1300000; }
    else if (e < 1900000) { dstp = em + 300000;  rowOff = 550000; le = e - 1600000; }
    else if (e < 2200000) { dstp = em;           rowOff = 650000; le = e - 1900000; }
    else if (e < 2300000) { dstp = ein + 100000; rowOff = 700000; le = e - 2200000; }
    else                  { dstp = ein;          rowOff = 702000; le = e - 2300000; }
    atomicAdd(&cnt[rowOff + dstp[le]], 1);
}

__global__ void scan1_kernel(const int* __restrict__ cnt, int* __restrict__ rowptr,
                             int* __restrict__ bsums, int n)
{
    __shared__ int wsums[8];
    int base = blockIdx.x * 4096 + threadIdx.x * 16;
    int v[16];
    int s = 0;
#pragma unroll
    for (int i = 0; i < 16; i++) {
        v[i] = (base + i < n) ? cnt[base + i] : 0;
        s += v[i];
    }
    int lane = threadIdx.x & 31, w = threadIdx.x >> 5;
    int ps = s;
#pragma unroll
    for (int o = 1; o < 32; o <<= 1) {
        int t = __shfl_up_sync(0xffffffffu, ps, o);
        if (lane >= o) ps += t;
    }
    if (lane == 31) wsums[w] = ps;
    __syncthreads();
    if (w == 0) {
        int t = (lane < 8) ? wsums[lane] : 0;
#pragma unroll
        for (int o = 1; o < 8; o <<= 1) {
            int u = __shfl_up_sync(0xffffffffu, t, o);
            if (lane >= o) t += u;
        }
        if (lane < 8) wsums[lane] = t;
    }
    __syncthreads();
    int excl = ps - s + (w ? wsums[w - 1] : 0);
    int run = excl;
#pragma unroll
    for (int i = 0; i < 16; i++) {
        if (base + i < n) rowptr[base + i] = run;
        run += v[i];
    }
    if (threadIdx.x == 0) bsums[blockIdx.x] = wsums[7];
}

__global__ void scan2_kernel(int* __restrict__ bsums, int nb)
{
    if (threadIdx.x == 0 && blockIdx.x == 0) {
        int run = 0;
        for (int i = 0; i < nb; i++) {
            int t = bsums[i];
            bsums[i] = run;
            run += t;
        }
    }
}

// scan3 also copies final rowptr into cursor (saves the memcpy launch)
__global__ void scan3_kernel(int* __restrict__ rowptr, const int* __restrict__ bsums,
                             int* __restrict__ cursor, int n)
{
    int base = blockIdx.x * 4096 + threadIdx.x * 16;
    int off = bsums[blockIdx.x];
#pragma unroll
    for (int i = 0; i < 16; i++)
        if (base + i < n) {
            int v = rowptr[base + i] + off;
            rowptr[base + i] = v;
            cursor[base + i] = v;
        }
    if (blockIdx.x == 0 && threadIdx.x == 0) rowptr[n] = ETOT;
}

// ---------------------------------------------------------------------------
// merged CSR fill
// ---------------------------------------------------------------------------
__global__ void csr_fill(const int* __restrict__ eb, const int* __restrict__ es,
                         const int* __restrict__ em, const int* __restrict__ ein,
                         const float* __restrict__ w0, const float* __restrict__ w1,
                         const float* __restrict__ w2, const float* __restrict__ w3,
                         const float* __restrict__ w4, const float* __restrict__ w5,
                         const float* __restrict__ w6, const float* __restrict__ w7,
                         int* __restrict__ cursor, int* __restrict__ srcg,
                         float* __restrict__ wg)
{
    int e = blockIdx.x * 256 + threadIdx.x;
    if (e >= ETOT) return;
    const int *dstp, *srcp; const float* ewp; int rowOff, le;
    if      (e <  500000) { dstp = eb + 500000;  srcp = eb;           ewp = w0; rowOff = 0;      le = e; }
    else if (e < 1000000) { dstp = eb;           srcp = eb + 500000;  ewp = w1; rowOff = 100000; le = e - 500000; }
    else if (e < 1300000) { dstp = es + 300000;  srcp = es;           ewp = w2; rowOff = 300000; le = e - 1000000; }
    else if (e < 1600000) { dstp = es;           srcp = es + 300000;  ewp = w3; rowOff = 350000; le = e - 1300000; }
    else if (e < 1900000) { dstp = em + 300000;  srcp = em;           ewp = w4; rowOff = 550000; le = e - 1600000; }
    else if (e < 2200000) { dstp = em;           srcp = em + 300000;  ewp = w5; rowOff = 650000; le = e - 1900000; }
    else if (e < 2300000) { dstp = ein + 100000; srcp = ein;          ewp = w6; rowOff = 700000; le = e - 2200000; }
    else                  { dstp = ein;          srcp = ein + 100000; ewp = w7; rowOff = 702000; le = e - 2300000; }
    int slot = atomicAdd(&cursor[rowOff + dstp[le]], 1);
    srcg[slot] = srcp[le];
    wg[slot]   = ewp[le];
}

// ---------------------------------------------------------------------------
// combined Wl / bias per (layer, dst type)
// ---------------------------------------------------------------------------
__global__ void wsum_kernel(const float* __restrict__ W1l, const float* __restrict__ b1,
                            const float* __restrict__ W2l, const float* __restrict__ b2,
                            float* __restrict__ wsum, float* __restrict__ bsum)
{
    const int dstT[8] = {1, 0, 3, 0, 1, 3, 2, 1};
    int idx = blockIdx.x * blockDim.x + threadIdx.x;
    if (idx >= 2 * 4 * HID * HID) return;
    int l  = idx / (4 * HID * HID);
    int r  = idx % (4 * HID * HID);
    int d  = r / (HID * HID);
    int ij = r % (HID * HID);
    const float* W = l ? W2l : W1l;
    float s = 0.f;
#pragma unroll
    for (int t = 0; t < 8; t++)
        if (dstT[t] == d) s += W[t * HID * HID + ij];
    wsum[idx] = s;
    if (ij < HID) {
        const float* B = l ? b2 : b1;
        float sb = 0.f;
#pragma unroll
        for (int t = 0; t < 8; t++)
            if (dstT[t] == d) sb += B[t * HID + ij];
        bsum[(l * 4 + d) * HID + ij] = sb;
    }
}

__global__ void wsplit_kernel(const float* __restrict__ wsum,
                              const float* __restrict__ W1r,
                              const float* __restrict__ W2r,
                              __nv_bfloat16* __restrict__ wh,
                              __nv_bfloat16* __restrict__ wl)
{
    int idx = blockIdx.x * blockDim.x + threadIdx.x;
    if (idx >= NWCHUNK * HID * HID) return;
    int c  = idx >> 14;
    int ij = idx & 16383;
    float v = (c < 8) ? wsum[idx]
            : (c < 16) ? W1r[(c - 8) * HID * HID + ij]
                       : W2r[(c - 16) * HID * HID + ij];
    __nv_bfloat16 h = __float2bfloat16(v);
    wh[idx] = h;
    wl[idx] = __float2bfloat16(v - __bfloat162float(h));
}

// ---------------------------------------------------------------------------
// split x0 into xhi/xlo at concatenated node offsets
// ---------------------------------------------------------------------------
__global__ void xsplit_kernel(const float* __restrict__ xu, const float* __restrict__ xp,
                              const float* __restrict__ xc, const float* __restrict__ xq,
                              __nv_bfloat16* __restrict__ xhi, __nv_bfloat16* __restrict__ xlo)
{
    int i = blockIdx.x * 256 + threadIdx.x;          // float4 index
    if (i >= NTOT * 32) return;
    int row = i >> 5;
    int c4  = i & 31;
    const float* x;
    int lrow;
    if      (row < NU)           { x = xu; lrow = row; }
    else if (row < NU + NP)      { x = xp; lrow = row - NU; }
    else if (row < NU + NP + NC) { x = xc; lrow = row - NU - NP; }
    else                         { x = xq; lrow = row - NU - NP - NC; }
    float4 v = *((const float4*)(x + (size_t)lrow * HID) + c4);
    uint32_t h01, l01, h23, l23;
    split_pair(v.x, v.y, h01, l01);
    split_pair(v.z, v.w, h23, l23);
    size_t off = (size_t)row * HID + c4 * 4;
    *(uint2*)(xhi + off) = make_uint2(h01, h23);
    *(uint2*)(xlo + off) = make_uint2(l01, l23);
}

// ---------------------------------------------------------------------------
// merged CSR gather (layer 0: fp32 x0 tables). One warp per (relation,dst) row.
// ---------------------------------------------------------------------------
__global__ void gather_x0(const float* __restrict__ xu, const float* __restrict__ xp,
                          const float* __restrict__ xc, const float* __restrict__ xq,
                          const int* __restrict__ rowptr, const int* __restrict__ srcg,
                          const float* __restrict__ wg,
                          __nv_bfloat16* __restrict__ ahi, __nv_bfloat16* __restrict__ alo)
{
    int row = (blockIdx.x * blockDim.x + threadIdx.x) >> 5;
    int lane = threadIdx.x & 31;
    if (row >= NROWS) return;
    const float* x = (row <  100000) ? xu
                   : (row <  300000) ? xp
                   : (row <  350000) ? xu
                   : (row <  550000) ? xq
                   : (row <  650000) ? xq
                   : (row <  700000) ? xp
                   : (row <  702000) ? xp : xc;

    int e0 = rowptr[row], e1 = rowptr[row + 1];
    float4 acc = make_float4(0.f, 0.f, 0.f, 0.f);
    int e = e0;
    for (; e + 1 < e1; e += 2) {
        int   s0 = srcg[e],  s1 = srcg[e + 1];
        float w0 = wg[e],    w1 = wg[e + 1];
        float4 v0 = *((const float4*)(x + (size_t)s0 * HID) + lane);
        float4 v1 = *((const float4*)(x + (size_t)s1 * HID) + lane);
        acc.x += w0 * v0.x + w1 * v1.x;
        acc.y += w0 * v0.y + w1 * v1.y;
        acc.z += w0 * v0.z + w1 * v1.z;
        acc.w += w0 * v0.w + w1 * v1.w;
    }
    if (e < e1) {
        int s0 = srcg[e];
        float w0 = wg[e];
        float4 v0 = *((const float4*)(x + (size_t)s0 * HID) + lane);
        acc.x += w0 * v0.x; acc.y += w0 * v0.y;
        acc.z += w0 * v0.z; acc.w += w0 * v0.w;
    }
    float invd = 1.f / fmaxf((float)(e1 - e0), 1.f);
    acc.x *= invd; acc.y *= invd; acc.z *= invd; acc.w *= invd;
    uint32_t h01, l01, h23, l23;
    split_pair(acc.x, acc.y, h01, l01);
    split_pair(acc.z, acc.w, h23, l23);
    size_t off = (size_t)row * HID + lane * 4;
    *(uint2*)(ahi + off) = make_uint2(h01, h23);
    *(uint2*)(alo + off) = make_uint2(l01, l23);
}

// ---------------------------------------------------------------------------
// merged CSR gather (layer 1: fp32 h, concatenated layout -> offset LUT)
// ---------------------------------------------------------------------------
__global__ void gather_h(const float* __restrict__ h,
                         const int* __restrict__ rowptr, const int* __restrict__ srcg,
                         const float* __restrict__ wg,
                         __nv_bfloat16* __restrict__ ahi, __nv_bfloat16* __restrict__ alo)
{
    int row = (blockIdx.x * blockDim.x + threadIdx.x) >> 5;
    int lane = threadIdx.x & 31;
    if (row >= NROWS) return;
    const size_t OU = 0, OP = (size_t)NU * HID, OC = (size_t)(NU + NP) * HID,
                 OQ = (size_t)(NU + NP + NC) * HID;
    size_t xo = (row <  100000) ? OU
              : (row <  300000) ? OP
              : (row <  350000) ? OU
              : (row <  550000) ? OQ
              : (row <  650000) ? OQ
              : (row <  700000) ? OP
              : (row <  702000) ? OP : OC;
    const float* x = h + xo;

    int e0 = rowptr[row], e1 = rowptr[row + 1];
    float4 acc = make_float4(0.f, 0.f, 0.f, 0.f);
    int e = e0;
    for (; e + 1 < e1; e += 2) {
        int   s0 = srcg[e],  s1 = srcg[e + 1];
        float w0 = wg[e],    w1 = wg[e + 1];
        float4 v0 = *((const float4*)(x + (size_t)s0 * HID) + lane);
        float4 v1 = *((const float4*)(x + (size_t)s1 * HID) + lane);
        acc.x += w0 * v0.x + w1 * v1.x;
        acc.y += w0 * v0.y + w1 * v1.y;
        acc.z += w0 * v0.z + w1 * v1.z;
        acc.w += w0 * v0.w + w1 * v1.w;
    }
    if (e < e1) {
        int s0 = srcg[e];
        float w0 = wg[e];
        float4 v0 = *((const float4*)(x + (size_t)s0 * HID) + lane);
        acc.x += w0 * v0.x; acc.y += w0 * v0.y;
        acc.z += w0 * v0.z; acc.w += w0 * v0.w;
    }
    float invd = 1.f / fmaxf((float)(e1 - e0), 1.f);
    acc.x *= invd; acc.y *= invd; acc.z *= invd; acc.w *= invd;
    uint32_t h01, l01, h23, l23;
    split_pair(acc.x, acc.y, h01, l01);
    split_pair(acc.z, acc.w, h23, l23);
    size_t off = (size_t)row * HID + lane * 4;
    *(uint2*)(ahi + off) = make_uint2(h01, h23);
    *(uint2*)(alo + off) = make_uint2(l01, l23);
}

// ---------------------------------------------------------------------------
// host launch
// ---------------------------------------------------------------------------
extern "C" void kernel_launch(void* const* d_in, const int* in_sizes, int n_in,
                              void* d_out, int out_size)
{
    (void)in_sizes; (void)n_in; (void)out_size;

    static const int rowOffR[8] = {0, 100000, 300000, 350000, 550000, 650000, 700000, 702000};
    static const int relForDst[4][3] = { {1, 3, -1}, {0, 4, 7}, {6, -1, -1}, {2, 5, -1} };
    static const int nRelForDst[4]   = { 2, 3, 1, 2 };
    static const int    nodeN[4]   = {NU, NP, NC, NQ};
    static const size_t nodeOff[4] = {0, NU, NU + NP, NU + NP + NC};

    cudaFuncSetAttribute(gemm_mma, cudaFuncAttributeMaxDynamicSharedMemorySize, GSMEM);

    float *hbuf, *wsum, *bsum, *wg;
    __nv_bfloat16 *ahi, *alo, *xhi, *xlo, *wh, *wl;
    int *cnt, *rowptr, *cursor, *srcg, *bsums;
    cudaGetSymbolAddress((void**)&ahi,    g_ahi);
    cudaGetSymbolAddress((void**)&alo,    g_alo);
    cudaGetSymbolAddress((void**)&xhi,    g_xhi);
    cudaGetSymbolAddress((void**)&xlo,    g_xlo);
    cudaGetSymbolAddress((void**)&hbuf,   g_h);
    cudaGetSymbolAddress((void**)&cnt,    g_cnt);
    cudaGetSymbolAddress((void**)&rowptr, g_rowptr);
    cudaGetSymbolAddress((void**)&cursor, g_cursor);
    cudaGetSymbolAddress((void**)&srcg,   g_srcg);
    cudaGetSymbolAddress((void**)&wg,     g_wg);
    cudaGetSymbolAddress((void**)&bsums,  g_bsums);
    cudaGetSymbolAddress((void**)&wsum,   g_wsum);
    cudaGetSymbolAddress((void**)&bsum,   g_bsum);
    cudaGetSymbolAddress((void**)&wh,     g_wh);
    cudaGetSymbolAddress((void**)&wl,     g_wl);

    const float* xu = (const float*)d_in[0];
    const float* xp = (const float*)d_in[1];
    const float* xc = (const float*)d_in[2];
    const float* xq = (const float*)d_in[3];
    const float* W1l = (const float*)d_in[4];
    const float* b1  = (const float*)d_in[5];
    const float* W1r = (const float*)d_in[6];
    const float* W2l = (const float*)d_in[7];
    const float* b2  = (const float*)d_in[8];
    const float* W2r = (const float*)d_in[9];
    const int* eb  = (const int*)d_in[18];
    const int* es  = (const int*)d_in[19];
    const int* em  = (const int*)d_in[20];
    const int* ein = (const int*)d_in[21];
    float* out = (float*)d_out;

    cudaStream_t st = 0;
    const int NSCAN = (NROWS + 4095) / 4096;

    // ---- CSR build ----
    cudaMemsetAsync(cnt, 0, NROWS * sizeof(int), st);
    csr_count<<<(ETOT + 255) / 256, 256, 0, st>>>(eb, es, em, ein, cnt);
    scan1_kernel<<<NSCAN, 256, 0, st>>>(cnt, rowptr, bsums, NROWS);
    scan2_kernel<<<1, 32, 0, st>>>(bsums, NSCAN);
    scan3_kernel<<<NSCAN, 256, 0, st>>>(rowptr, bsums, cursor, NROWS);
    csr_fill<<<(ETOT + 255) / 256, 256, 0, st>>>(
        eb, es, em, ein,
        (const float*)d_in[10], (const float*)d_in[11], (const float*)d_in[12],
        (const float*)d_in[13], (const float*)d_in[14], (const float*)d_in[15],
        (const float*)d_in[16], (const float*)d_in[17],
        cursor, srcg, wg);

    // ---- weights + x split ----
    wsum_kernel<<<(2 * 4 * HID * HID + 255) / 256, 256, 0, st>>>(W1l, b1, W2l, b2, wsum, bsum);
    wsplit_kernel<<<(NWCHUNK * HID * HID + 255) / 256, 256, 0, st>>>(wsum, W1r, W2r, wh, wl);
    xsplit_kernel<<<(NTOT * 32 + 255) / 256, 256, 0, st>>>(xu, xp, xc, xq, xhi, xlo);

    // ---- two layers ----
    for (int layer = 0; layer < 2; layer++) {
        if (layer == 0)
            gather_x0<<<(NROWS * 32 + 255) / 256, 256, 0, st>>>(
                xu, xp, xc, xq, rowptr, srcg, wg, ahi, alo);
        else
            gather_h<<<(NROWS * 32 + 255) / 256, 256, 0, st>>>(
                hbuf, rowptr, srcg, wg, ahi, alo);

        for (int d = 0; d < 4; d++) {
            const __nv_bfloat16 *Ah[3] = {nullptr, nullptr, nullptr};
            const __nv_bfloat16 *Al[3] = {nullptr, nullptr, nullptr};
            const __nv_bfloat16 *Whp[4] = {nullptr, nullptr, nullptr, nullptr};
            const __nv_bfloat16 *Wlp[4] = {nullptr, nullptr, nullptr, nullptr};
            Whp[0] = wh + (size_t)(layer * 4 + d) * HID * HID;
            Wlp[0] = wl + (size_t)(layer * 4 + d) * HID * HID;
            for (int q = 0; q < nRelForDst[d]; q++) {
                int t = relForDst[d][q];
                Ah[q] = ahi + (size_t)rowOffR[t] * HID;
                Al[q] = alo + (size_t)rowOffR[t] * HID;
                Whp[q + 1] = wh + (size_t)(8 + layer * 8 + t) * HID * HID;
                Wlp[q + 1] = wl + (size_t)(8 + layer * 8 + t) * HID * HID;
            }
            GemmArgs p;
            p.A0f = layer ? (hbuf + nodeOff[d] * HID) : nullptr;
            p.A0h = layer ? nullptr : (xhi + nodeOff[d] * HID);
            p.A0l = layer ? nullptr : (xlo + nodeOff[d] * HID);
            p.A1h = Ah[0]; p.A1l = Al[0];
            p.A2h = Ah[1]; p.A2l = Al[1];
            p.A3h = Ah[2]; p.A3l = Al[2];
            p.W0h = Whp[0]; p.W0l = Wlp[0];
            p.W1h = Whp[1]; p.W1l = Wlp[1];
            p.W2h = Whp[2]; p.W2l = Wlp[2];
            p.W3h = Whp[3]; p.W3l = Wlp[3];
            int nch = 1 + nRelForDst[d];
            float* C = layer ? (out + nodeOff[d] * HID) : (hbuf + nodeOff[d] * HID);
            gemm_mma<<<(nodeN[d] + 127) / 128, 256, GSMEM, st>>>(
                p, nch, layer == 0 ? 1 : 0, bsum + (layer * 4 + d) * HID, C,
                nodeN[d], layer == 0 ? 1 : 0);
        }
    }
}

// round 10
// speedup vs baseline: 1.0382x; 1.0382x over previous
#include <cuda_runtime.h>
#include <cuda_bf16.h>
#include <stdint.h>

// ---------------------------------------------------------------------------
// HeteroGraphSAGE, 2 layers, 4 node types, 8 relations.
// agg[d] = Wr * (inv[d] * sum_e w_e * x[src])  -> per-relation CSR gather (no
// atomics) of RAW features, written in split-bf16 (hi+lo); one K-concat
// tensor-core GEMM per dst type, templated on (NCH, A0SPLIT) so every fill
// path is compile-time selected (no runtime branch register bloat).
// ---------------------------------------------------------------------------

#define NU 200000
#define NP 100000
#define NC 2000
#define NQ 50000
#define NTOT 352000
#define HID 128

#define NROWS 802000        // total (relation, dst-node) rows
#define ETOT  2400000       // total directed edges
#define NWCHUNK 24          // 8 wsum + 8 W1r + 8 W2r

#define LDS 72              // bf16 elems per smem row (64 data + 8 pad -> 144B stride)
#define LDSB 144
#define TILE_B (128 * LDSB)
#define SMEM_BYTES (4 * TILE_B)      // Ah, Al, Wh, Wl = 73728 B (occupancy 2)

// scratch (device globals; allocation-free)
__device__ __nv_bfloat16 g_ahi[(size_t)NROWS * HID];   // aggr hi
__device__ __nv_bfloat16 g_alo[(size_t)NROWS * HID];   // aggr lo
__device__ __nv_bfloat16 g_xhi[(size_t)NTOT * HID];    // x0 pre-split hi
__device__ __nv_bfloat16 g_xlo[(size_t)NTOT * HID];    // x0 pre-split lo
__device__ float g_h[(size_t)NTOT * HID];              // hidden after layer 1 (fp32)
__device__ int   g_cnt[NROWS];
__device__ int   g_rowptr[NROWS + 1];
__device__ int   g_cursor[NROWS];
__device__ int   g_srcg[ETOT];
__device__ float g_wg[ETOT];
__device__ int   g_bsums[512];
__device__ float g_wsum[2 * 4 * HID * HID];
__device__ float g_bsum[2 * 4 * HID];
__device__ __nv_bfloat16 g_wh[NWCHUNK * HID * HID];
__device__ __nv_bfloat16 g_wl[NWCHUNK * HID * HID];

// ---------------------------------------------------------------------------
// PTX helpers
// ---------------------------------------------------------------------------
#define LDSM4(R, addr)                                                          \
    asm volatile("ldmatrix.sync.aligned.m8n8.x4.shared.b16 {%0,%1,%2,%3}, [%4];" \
                 : "=r"((R)[0]), "=r"((R)[1]), "=r"((R)[2]), "=r"((R)[3])        \
                 : "r"(addr))

#define MMA16816(C, A, B0, B1)                                                  \
    asm volatile("mma.sync.aligned.m16n8k16.row.col.f32.bf16.bf16.f32 "         \
                 "{%0,%1,%2,%3},{%4,%5,%6,%7},{%8,%9},{%0,%1,%2,%3};"           \
                 : "+f"((C)[0]), "+f"((C)[1]), "+f"((C)[2]), "+f"((C)[3])        \
                 : "r"((A)[0]), "r"((A)[1]), "r"((A)[2]), "r"((A)[3]),           \
                   "r"(B0), "r"(B1))

__device__ __forceinline__ uint32_t pack_bf16(__nv_bfloat16 a, __nv_bfloat16 b)
{
    __nv_bfloat162 p = __halves2bfloat162(a, b);
    return *reinterpret_cast<uint32_t*>(&p);
}

__device__ __forceinline__ void split_pair(float x, float y, uint32_t& hi, uint32_t& lo)
{
    __nv_bfloat16 hx = __float2bfloat16(x);
    __nv_bfloat16 hy = __float2bfloat16(y);
    __nv_bfloat16 lx = __float2bfloat16(x - __bfloat162float(hx));
    __nv_bfloat16 ly = __float2bfloat16(y - __bfloat162float(hy));
    hi = pack_bf16(hx, hy);
    lo = pack_bf16(lx, ly);
}

// ---------------------------------------------------------------------------
// Multi-chunk tensor-core GEMM (bf16x3 split):
//   C = bias + A0 @ W0^T + sum_q Aq @ Wq^T
// Template NCH = number of K=128 chunks (compile-time unrolled, no guard).
// Template A0SPLIT: 1 -> chunk 0 is pre-split bf16 (pure copy fill);
//                   0 -> chunk 0 is fp32 (convert fill).
// Chunks 1..NCH-1 and all W chunks are always pre-split bf16.
// Block tile 128x128, 8 warps (4m x 2n), occupancy 2.
// ---------------------------------------------------------------------------
struct GemmArgs {
    const float* A0f;
    const __nv_bfloat16 *A0h, *A0l, *A1h, *A1l, *A2h, *A2l, *A3h, *A3l;
    const __nv_bfloat16 *W0h, *W0l, *W1h, *W1l, *W2h, *W2l, *W3h, *W3l;
};

template <int NCH, int A0SPLIT>
__global__ void __launch_bounds__(256, 2)
gemm_mma(GemmArgs p, const float* __restrict__ bias,
         float* __restrict__ C, int n, int dorelu)
{
    extern __shared__ __nv_bfloat16 smem[];
    uint32_t sb = (uint32_t)__cvta_generic_to_shared(smem);

    const int tid  = threadIdx.x;
    const int lane = tid & 31;
    const int warp = tid >> 5;
    const int wm = warp >> 1;
    const int wn = warp & 1;
    const int bm = blockIdx.x * 128;

    float c[2][8][4];
#pragma unroll
    for (int i = 0; i < 2; i++)
#pragma unroll
        for (int j = 0; j < 8; j++)
#pragma unroll
            for (int q = 0; q < 4; q++) c[i][j][q] = 0.f;

#pragma unroll
    for (int ch = 0; ch < NCH; ch++) {
        // compile-time pointer selection per unrolled iteration
        const __nv_bfloat16* Wh = (ch == 0) ? p.W0h : (ch == 1) ? p.W1h
                                : (ch == 2) ? p.W2h : p.W3h;
        const __nv_bfloat16* Wl = (ch == 0) ? p.W0l : (ch == 1) ? p.W1l
                                : (ch == 2) ? p.W2l : p.W3l;
        const __nv_bfloat16* Ahi = (ch == 0) ? p.A0h : (ch == 1) ? p.A1h
                                 : (ch == 2) ? p.A2h : p.A3h;
        const __nv_bfloat16* Alo = (ch == 0) ? p.A0l : (ch == 1) ? p.A1l
                                 : (ch == 2) ? p.A2l : p.A3l;

        for (int kb = 0; kb < 128; kb += 64) {
            // ---- A fill (path chosen at compile time) ----
            if (ch == 0 && !A0SPLIT) {
                // fp32 -> split-bf16 conversion path
#pragma unroll
                for (int it = 0; it < 8; it++) {
                    int idx = tid + it * 256;
                    int r   = idx >> 4;
                    int kc  = (idx & 15) << 2;
                    float4 va = make_float4(0.f, 0.f, 0.f, 0.f);
                    int row = bm + r;
                    if (row < n)
                        va = *(const float4*)(p.A0f + (size_t)row * HID + kb + kc);
                    uint32_t h01, l01, h23, l23;
                    split_pair(va.x, va.y, h01, l01);
                    split_pair(va.z, va.w, h23, l23);
                    size_t so = (size_t)r * LDS + kc;
                    *(uint2*)(smem + so)             = make_uint2(h01, h23);
                    *(uint2*)(smem + 128 * LDS + so) = make_uint2(l01, l23);
                }
            } else {
                // direct copy of pre-split bf16 (16B per load)
                const uint4 z = make_uint4(0, 0, 0, 0);
#pragma unroll
                for (int it = 0; it < 4; it++) {
                    int idx = tid + it * 256;          // 0..1023
                    int r   = idx >> 3;
                    int kc  = (idx & 7) << 3;
                    int row = bm + r;
                    size_t go = (size_t)row * HID + kb + kc;
                    size_t so = (size_t)r * LDS + kc;
                    uint4 vh = (row < n) ? *(const uint4*)(Ahi + go) : z;
                    uint4 vl = (row < n) ? *(const uint4*)(Alo + go) : z;
                    *(uint4*)(smem + so)             = vh;
                    *(uint4*)(smem + 128 * LDS + so) = vl;
                }
            }
            // ---- W fill (pre-split, direct copy) ----
#pragma unroll
            for (int it = 0; it < 4; it++) {
                int idx = tid + it * 256;
                int r   = idx >> 3;
                int kc  = (idx & 7) << 3;
                size_t go = (size_t)r * HID + kb + kc;
                size_t so = (size_t)r * LDS + kc;
                *(uint4*)(smem + 2 * 128 * LDS + so) = *(const uint4*)(Wh + go);
                *(uint4*)(smem + 3 * 128 * LDS + so) = *(const uint4*)(Wl + go);
            }
            __syncthreads();

            // ---- 4 k-steps of 16 ----
#pragma unroll
            for (int ks = 0; ks < 4; ks++) {
                uint32_t ah[2][4], al[2][4], bh[4][4], bl[4][4];
#pragma unroll
                for (int i = 0; i < 2; i++) {
                    int r   = wm * 32 + i * 16 + (lane & 15);
                    int kby = ks * 32 + ((lane >> 4) << 4);
                    uint32_t ad = sb + r * LDSB + kby;
                    LDSM4(ah[i], ad);
                    LDSM4(al[i], ad + TILE_B);
                }
#pragma unroll
                for (int pq = 0; pq < 4; pq++) {
                    int nr  = wn * 64 + (2 * pq + (lane >> 4)) * 8 + (lane & 7);
                    int kby = ks * 32 + ((lane >> 3) & 1) * 16;
                    uint32_t ad = sb + 2 * TILE_B + nr * LDSB + kby;
                    LDSM4(bh[pq], ad);
                    LDSM4(bl[pq], ad + TILE_B);
                }
#pragma unroll
                for (int i = 0; i < 2; i++)
#pragma unroll
                    for (int j = 0; j < 8; j++) {
                        const uint32_t* b = bh[j >> 1] + (j & 1) * 2;
                        MMA16816(c[i][j], ah[i], b[0], b[1]);
                    }
#pragma unroll
                for (int i = 0; i < 2; i++)
#pragma unroll
                    for (int j = 0; j < 8; j++) {
                        const uint32_t* b = bl[j >> 1] + (j & 1) * 2;
                        MMA16816(c[i][j], ah[i], b[0], b[1]);
                    }
#pragma unroll
                for (int i = 0; i < 2; i++)
#pragma unroll
                    for (int j = 0; j < 8; j++) {
                        const uint32_t* b = bh[j >> 1] + (j & 1) * 2;
                        MMA16816(c[i][j], al[i], b[0], b[1]);
                    }
            }
            __syncthreads();
        }
    }

    // ---- epilogue ----
    const int g  = lane >> 2;
    const int tq = lane & 3;
#pragma unroll
    for (int i = 0; i < 2; i++) {
#pragma unroll
        for (int half = 0; half < 2; half++) {
            int row = bm + wm * 32 + i * 16 + half * 8 + g;
            if (row >= n) continue;
#pragma unroll
            for (int j = 0; j < 8; j++) {
                int col = wn * 64 + j * 8 + tq * 2;
                float vx = c[i][j][half * 2 + 0] + bias[col];
                float vy = c[i][j][half * 2 + 1] + bias[col + 1];
                if (dorelu) {
                    vx = fmaxf(vx, 0.f);
                    vy = fmaxf(vy, 0.f);
                }
                *(float2*)(C + (size_t)row * HID + col) = make_float2(vx, vy);
            }
        }
    }
}

// ---------------------------------------------------------------------------
// CSR build: count -> scan -> fill (per relation, proven structure)
// ---------------------------------------------------------------------------
__global__ void count_kernel(const int* __restrict__ dst, int E, int* __restrict__ cnt)
{
    int e = blockIdx.x * blockDim.x + threadIdx.x;
    if (e < E) atomicAdd(&cnt[dst[e]], 1);
}

__global__ void scan1_kernel(const int* __restrict__ cnt, int* __restrict__ rowptr,
                             int* __restrict__ bsums, int n)
{
    __shared__ int wsums[8];
    int base = blockIdx.x * 4096 + threadIdx.x * 16;
    int v[16];
    int s = 0;
#pragma unroll
    for (int i = 0; i < 16; i++) {
        v[i] = (base + i < n) ? cnt[base + i] : 0;
        s += v[i];
    }
    int lane = threadIdx.x & 31, w = threadIdx.x >> 5;
    int ps = s;
#pragma unroll
    for (int o = 1; o < 32; o <<= 1) {
        int t = __shfl_up_sync(0xffffffffu, ps, o);
        if (lane >= o) ps += t;
    }
    if (lane == 31) wsums[w] = ps;
    __syncthreads();
    if (w == 0) {
        int t = (lane < 8) ? wsums[lane] : 0;
#pragma unroll
        for (int o = 1; o < 8; o <<= 1) {
            int u = __shfl_up_sync(0xffffffffu, t, o);
            if (lane >= o) t += u;
        }
        if (lane < 8) wsums[lane] = t;
    }
    __syncthreads();
    int excl = ps - s + (w ? wsums[w - 1] : 0);
    int run = excl;
#pragma unroll
    for (int i = 0; i < 16; i++) {
        if (base + i < n) rowptr[base + i] = run;
        run += v[i];
    }
    if (threadIdx.x == 0) bsums[blockIdx.x] = wsums[7];
}

__global__ void scan2_kernel(int* __restrict__ bsums, int nb)
{
    if (threadIdx.x == 0 && blockIdx.x == 0) {
        int run = 0;
        for (int i = 0; i < nb; i++) {
            int t = bsums[i];
            bsums[i] = run;
            run += t;
        }
    }
}

// scan3 also initializes cursor (saves the 3.2MB memcpy launch)
__global__ void scan3_kernel(int* __restrict__ rowptr, const int* __restrict__ bsums,
                             int* __restrict__ cursor, int n)
{
    int base = blockIdx.x * 4096 + threadIdx.x * 16;
    int off = bsums[blockIdx.x];
#pragma unroll
    for (int i = 0; i < 16; i++)
        if (base + i < n) {
            int v = rowptr[base + i] + off;
            rowptr[base + i] = v;
            cursor[base + i] = v;
        }
    if (blockIdx.x == 0 && threadIdx.x == 0) rowptr[n] = ETOT;
}

__global__ void fill_kernel(const int* __restrict__ src, const int* __restrict__ dst,
                            const float* __restrict__ ew, int E, int rowOff,
                            int* __restrict__ cursor,
                            int* __restrict__ srcg, float* __restrict__ wg)
{
    int e = blockIdx.x * blockDim.x + threadIdx.x;
    if (e >= E) return;
    int slot = atomicAdd(&cursor[rowOff + dst[e]], 1);
    srcg[slot] = src[e];
    wg[slot]   = ew[e];
}

// ---------------------------------------------------------------------------
// Combined Wl / bias per (layer, dst type).
// ---------------------------------------------------------------------------
__global__ void wsum_kernel(const float* __restrict__ W1l, const float* __restrict__ b1,
                            const float* __restrict__ W2l, const float* __restrict__ b2,
                            float* __restrict__ wsum, float* __restrict__ bsum)
{
    const int dstT[8] = {1, 0, 3, 0, 1, 3, 2, 1};
    int idx = blockIdx.x * blockDim.x + threadIdx.x;
    if (idx >= 2 * 4 * HID * HID) return;
    int l  = idx / (4 * HID * HID);
    int r  = idx % (4 * HID * HID);
    int d  = r / (HID * HID);
    int ij = r % (HID * HID);
    const float* W = l ? W2l : W1l;
    float s = 0.f;
#pragma unroll
    for (int t = 0; t < 8; t++)
        if (dstT[t] == d) s += W[t * HID * HID + ij];
    wsum[idx] = s;
    if (ij < HID) {
        const float* B = l ? b2 : b1;
        float sb = 0.f;
#pragma unroll
        for (int t = 0; t < 8; t++)
            if (dstT[t] == d) sb += B[t * HID + ij];
        bsum[(l * 4 + d) * HID + ij] = sb;
    }
}

// ---------------------------------------------------------------------------
// Pre-split all 24 weight chunks into bf16 hi/lo.
// ---------------------------------------------------------------------------
__global__ void wsplit_kernel(const float* __restrict__ wsum,
                              const float* __restrict__ W1r,
                              const float* __restrict__ W2r,
                              __nv_bfloat16* __restrict__ wh,
                              __nv_bfloat16* __restrict__ wl)
{
    int idx = blockIdx.x * blockDim.x + threadIdx.x;
    if (idx >= NWCHUNK * HID * HID) return;
    int c  = idx >> 14;
    int ij = idx & 16383;
    float v = (c < 8) ? wsum[idx]
            : (c < 16) ? W1r[(c - 8) * HID * HID + ij]
                       : W2r[(c - 16) * HID * HID + ij];
    __nv_bfloat16 h = __float2bfloat16(v);
    wh[idx] = h;
    wl[idx] = __float2bfloat16(v - __bfloat162float(h));
}

// ---------------------------------------------------------------------------
// split x0 into xhi/xlo at concatenated node offsets
// ---------------------------------------------------------------------------
__global__ void xsplit_kernel(const float* __restrict__ xu, const float* __restrict__ xp,
                              const float* __restrict__ xc, const float* __restrict__ xq,
                              __nv_bfloat16* __restrict__ xhi, __nv_bfloat16* __restrict__ xlo)
{
    int i = blockIdx.x * 256 + threadIdx.x;          // float4 index
    if (i >= NTOT * 32) return;
    int row = i >> 5;
    int c4  = i & 31;
    const float* x;
    int lrow;
    if      (row < NU)           { x = xu; lrow = row; }
    else if (row < NU + NP)      { x = xp; lrow = row - NU; }
    else if (row < NU + NP + NC) { x = xc; lrow = row - NU - NP; }
    else                         { x = xq; lrow = row - NU - NP - NC; }
    float4 v = *((const float4*)(x + (size_t)lrow * HID) + c4);
    uint32_t h01, l01, h23, l23;
    split_pair(v.x, v.y, h01, l01);
    split_pair(v.z, v.w, h23, l23);
    size_t off = (size_t)row * HID + c4 * 4;
    *(uint2*)(xhi + off) = make_uint2(h01, h23);
    *(uint2*)(xlo + off) = make_uint2(l01, l23);
}

// ---------------------------------------------------------------------------
// CSR gather (per relation): one warp per dst row — no atomics.
// Output written in split-bf16 form.
// ---------------------------------------------------------------------------
__global__ void gather_kernel(const float* __restrict__ x,
                              const int* __restrict__ rowptr,
                              const int* __restrict__ srcg,
                              const float* __restrict__ wg,
                              __nv_bfloat16* __restrict__ ahi,
                              __nv_bfloat16* __restrict__ alo,
                              int nrows, int rowOff)
{
    int row = (blockIdx.x * blockDim.x + threadIdx.x) >> 5;
    int lane = threadIdx.x & 31;
    if (row >= nrows) return;
    int g = rowOff + row;
    int e0 = rowptr[g], e1 = rowptr[g + 1];

    float4 acc = make_float4(0.f, 0.f, 0.f, 0.f);
    int e = e0;
    for (; e + 1 < e1; e += 2) {
        int   s0 = srcg[e],   s1 = srcg[e + 1];
        float w0 = wg[e],     w1 = wg[e + 1];
        float4 v0 = *((const float4*)(x + (size_t)s0 * HID) + lane);
        float4 v1 = *((const float4*)(x + (size_t)s1 * HID) + lane);
        acc.x += w0 * v0.x + w1 * v1.x;
        acc.y += w0 * v0.y + w1 * v1.y;
        acc.z += w0 * v0.z + w1 * v1.z;
        acc.w += w0 * v0.w + w1 * v1.w;
    }
    if (e < e1) {
        int s0 = srcg[e];
        float w0 = wg[e];
        float4 v0 = *((const float4*)(x + (size_t)s0 * HID) + lane);
        acc.x += w0 * v0.x;
        acc.y += w0 * v0.y;
        acc.z += w0 * v0.z;
        acc.w += w0 * v0.w;
    }
    float invd = 1.f / fmaxf((float)(e1 - e0), 1.f);
    acc.x *= invd; acc.y *= invd; acc.z *= invd; acc.w *= invd;

    uint32_t h01, l01, h23, l23;
    split_pair(acc.x, acc.y, h01, l01);
    split_pair(acc.z, acc.w, h23, l23);
    size_t off = (size_t)g * HID + lane * 4;
    *(uint2*)(ahi + off) = make_uint2(h01, h23);
    *(uint2*)(alo + off) = make_uint2(l01, l23);
}

// ---------------------------------------------------------------------------
// Host launch
// ---------------------------------------------------------------------------
struct Rel { int srcT, dstT, E, eiIdx, rev, ewIdx, rowOff; };

#define LAUNCH_GEMM(NCHV, A0V)                                                  \
    gemm_mma<NCHV, A0V><<<(nodeN[d] + 127) / 128, 256, SMEM_BYTES, st>>>(       \
        p, bsum + (layer * 4 + d) * HID, C, nodeN[d], layer == 0 ? 1 : 0)

extern "C" void kernel_launch(void* const* d_in, const int* in_sizes, int n_in,
                              void* d_out, int out_size)
{
    (void)in_sizes; (void)n_in; (void)out_size;

    static const Rel rels[8] = {
        {0, 1, 500000, 18, 0, 10, 0},       // user -> product  (buys)
        {1, 0, 500000, 18, 1, 11, 100000},  // product -> user  (rev buys)
        {0, 3, 300000, 19, 0, 12, 300000},  // user -> query    (searches)
        {3, 0, 300000, 19, 1, 13, 350000},  // query -> user    (rev searches)
        {3, 1, 300000, 20, 0, 14, 550000},  // query -> product (matches)
        {1, 3, 300000, 20, 1, 15, 650000},  // product -> query (rev matches)
        {1, 2, 100000, 21, 0, 16, 700000},  // product -> category (in)
        {2, 1, 100000, 21, 1, 17, 702000},  // category -> product (rev in)
    };
    static const int relForDst[4][3] = { {1, 3, -1}, {0, 4, 7}, {6, -1, -1}, {2, 5, -1} };
    static const int nRelForDst[4]   = { 2, 3, 1, 2 };
    static const int    nodeN[4]   = {NU, NP, NC, NQ};
    static const size_t nodeOff[4] = {0, NU, NU + NP, NU + NP + NC};

    cudaFuncSetAttribute(gemm_mma<2, 0>, cudaFuncAttributeMaxDynamicSharedMemorySize, SMEM_BYTES);
    cudaFuncSetAttribute(gemm_mma<3, 0>, cudaFuncAttributeMaxDynamicSharedMemorySize, SMEM_BYTES);
    cudaFuncSetAttribute(gemm_mma<4, 0>, cudaFuncAttributeMaxDynamicSharedMemorySize, SMEM_BYTES);
    cudaFuncSetAttribute(gemm_mma<2, 1>, cudaFuncAttributeMaxDynamicSharedMemorySize, SMEM_BYTES);
    cudaFuncSetAttribute(gemm_mma<3, 1>, cudaFuncAttributeMaxDynamicSharedMemorySize, SMEM_BYTES);
    cudaFuncSetAttribute(gemm_mma<4, 1>, cudaFuncAttributeMaxDynamicSharedMemorySize, SMEM_BYTES);

    float *hbuf, *wsum, *bsum, *wg;
    __nv_bfloat16 *ahi, *alo, *xhi, *xlo, *wh, *wl;
    int *cnt, *rowptr, *cursor, *srcg, *bsums;
    cudaGetSymbolAddress((void**)&ahi,    g_ahi);
    cudaGetSymbolAddress((void**)&alo,    g_alo);
    cudaGetSymbolAddress((void**)&xhi,    g_xhi);
    cudaGetSymbolAddress((void**)&xlo,    g_xlo);
    cudaGetSymbolAddress((void**)&hbuf,   g_h);
    cudaGetSymbolAddress((void**)&cnt,    g_cnt);
    cudaGetSymbolAddress((void**)&rowptr, g_rowptr);
    cudaGetSymbolAddress((void**)&cursor, g_cursor);
    cudaGetSymbolAddress((void**)&srcg,   g_srcg);
    cudaGetSymbolAddress((void**)&wg,     g_wg);
    cudaGetSymbolAddress((void**)&bsums,  g_bsums);
    cudaGetSymbolAddress((void**)&wsum,   g_wsum);
    cudaGetSymbolAddress((void**)&bsum,   g_bsum);
    cudaGetSymbolAddress((void**)&wh,     g_wh);
    cudaGetSymbolAddress((void**)&wl,     g_wl);

    const float* xu = (const float*)d_in[0];
    const float* xp = (const float*)d_in[1];
    const float* xc = (const float*)d_in[2];
    const float* xq = (const float*)d_in[3];
    const float* x0[4] = { xu, xp, xc, xq };
    const float* W1l = (const float*)d_in[4];
    const float* b1  = (const float*)d_in[5];
    const float* W1r = (const float*)d_in[6];
    const float* W2l = (const float*)d_in[7];
    const float* b2  = (const float*)d_in[8];
    const float* W2r = (const float*)d_in[9];
    float* out = (float*)d_out;

    cudaStream_t st = 0;
    const int NSCAN = (NROWS + 4095) / 4096;

    // ---- CSR build (layer-invariant) ----
    cudaMemsetAsync(cnt, 0, NROWS * sizeof(int), st);
    for (int t = 0; t < 8; t++) {
        const Rel& r = rels[t];
        const int* ei  = (const int*)d_in[r.eiIdx];
        const int* dst = r.rev ? ei : ei + r.E;
        count_kernel<<<(r.E + 255) / 256, 256, 0, st>>>(dst, r.E, cnt + r.rowOff);
    }
    scan1_kernel<<<NSCAN, 256, 0, st>>>(cnt, rowptr, bsums, NROWS);
    scan2_kernel<<<1, 32, 0, st>>>(bsums, NSCAN);
    scan3_kernel<<<NSCAN, 256, 0, st>>>(rowptr, bsums, cursor, NROWS);
    for (int t = 0; t < 8; t++) {
        const Rel& r = rels[t];
        const int* ei  = (const int*)d_in[r.eiIdx];
        const int* src = r.rev ? ei + r.E : ei;
        const int* dst = r.rev ? ei       : ei + r.E;
        const float* ew = (const float*)d_in[r.ewIdx];
        fill_kernel<<<(r.E + 255) / 256, 256, 0, st>>>(src, dst, ew, r.E, r.rowOff,
                                                       cursor, srcg, wg);
    }

    // ---- combined Wl / bias, pre-split weights, pre-split x0 ----
    wsum_kernel<<<(2 * 4 * HID * HID + 255) / 256, 256, 0, st>>>(W1l, b1, W2l, b2, wsum, bsum);
    wsplit_kernel<<<(NWCHUNK * HID * HID + 255) / 256, 256, 0, st>>>(wsum, W1r, W2r, wh, wl);
    xsplit_kernel<<<(NTOT * 32 + 255) / 256, 256, 0, st>>>(xu, xp, xc, xq, xhi, xlo);

    // ---- two layers ----
    for (int layer = 0; layer < 2; layer++) {
        // gather raw features per relation (no atomics)
        for (int t = 0; t < 8; t++) {
            const Rel& r = rels[t];
            const float* x = layer ? (hbuf + nodeOff[r.srcT] * HID) : x0[r.srcT];
            int nrows = nodeN[r.dstT];
            gather_kernel<<<(nrows * 32 + 255) / 256, 256, 0, st>>>(
                x, rowptr, srcg, wg, ahi, alo, nrows, r.rowOff);
        }

        // one K-concat GEMM per dst type
        for (int d = 0; d < 4; d++) {
            const __nv_bfloat16 *Ah[3] = {nullptr, nullptr, nullptr};
            const __nv_bfloat16 *Al[3] = {nullptr, nullptr, nullptr};
            const __nv_bfloat16 *Whp[4] = {nullptr, nullptr, nullptr, nullptr};
            const __nv_bfloat16 *Wlp[4] = {nullptr, nullptr, nullptr, nullptr};
            Whp[0] = wh + (size_t)(layer * 4 + d) * HID * HID;
            Wlp[0] = wl + (size_t)(layer * 4 + d) * HID * HID;
            for (int q = 0; q < nRelForDst[d]; q++) {
                int t = relForDst[d][q];
                Ah[q] = ahi + (size_t)rels[t].rowOff * HID;
                Al[q] = alo + (size_t)rels[t].rowOff * HID;
                Whp[q + 1] = wh + (size_t)(8 + layer * 8 + t) * HID * HID;
                Wlp[q + 1] = wl + (size_t)(8 + layer * 8 + t) * HID * HID;
            }
            GemmArgs p;
            p.A0f = layer ? (hbuf + nodeOff[d] * HID) : nullptr;
            p.A0h = layer ? nullptr : (xhi + nodeOff[d] * HID);
            p.A0l = layer ? nullptr : (xlo + nodeOff[d] * HID);
            p.A1h = Ah[0]; p.A1l = Al[0];
            p.A2h = Ah[1]; p.A2l = Al[1];
            p.A3h = Ah[2]; p.A3l = Al[2];
            p.W0h = Whp[0]; p.W0l = Wlp[0];
            p.W1h = Whp[1]; p.W1l = Wlp[1];
            p.W2h = Whp[2]; p.W2l = Wlp[2];
            p.W3h = Whp[3]; p.W3l = Wlp[3];
            int nch = 1 + nRelForDst[d];
            float* C = layer ? (out + nodeOff[d] * HID) : (hbuf + nodeOff[d] * HID);
            if (layer == 0) {
                if (nch == 2)      LAUNCH_GEMM(2, 1);
                else if (nch == 3) LAUNCH_GEMM(3, 1);
                else               LAUNCH_GEMM(4, 1);
            } else {
                if (nch == 2)      LAUNCH_GEMM(2, 0);
                else if (nch == 3) LAUNCH_GEMM(3, 0);
                else               LAUNCH_GEMM(4, 0);
            }
        }
    }
}

// round 11
// speedup vs baseline: 1.0686x; 1.0292x over previous
#include <cuda_runtime.h>
#include <cuda_bf16.h>
#include <stdint.h>

// ---------------------------------------------------------------------------
// HeteroGraphSAGE, 2 layers, 4 node types, 8 relations.
// agg[d] = Wr * (inv[d] * sum_e w_e * x[src])  -> per-relation CSR gather (no
// atomics) of RAW features, written in split-bf16 (hi+lo, produced anyway);
// one K-concat tensor-core GEMM per dst type, templated on NCH.
// Chunk 0 (x0 or h) stays fp32 and is converted in-kernel: pre-splitting it
// costs a 360MB pass (measured +100us across R7-R10) for hidden ALU savings.
// ---------------------------------------------------------------------------

#define NU 200000
#define NP 100000
#define NC 2000
#define NQ 50000
#define NTOT 352000
#define HID 128

#define NROWS 802000        // total (relation, dst-node) rows
#define ETOT  2400000       // total directed edges
#define NWCHUNK 24          // 8 wsum + 8 W1r + 8 W2r

#define LDS 72              // bf16 elems per smem row (64 data + 8 pad -> 144B stride)
#define LDSB 144
#define TILE_B (128 * LDSB)
#define SMEM_BYTES (4 * TILE_B)      // Ah, Al, Wh, Wl = 73728 B (occupancy 2)

// scratch (device globals; allocation-free)
__device__ __nv_bfloat16 g_ahi[(size_t)NROWS * HID];   // aggr hi
__device__ __nv_bfloat16 g_alo[(size_t)NROWS * HID];   // aggr lo
__device__ float g_h[(size_t)NTOT * HID];              // hidden after layer 1 (fp32)
__device__ int   g_cnt[NROWS];
__device__ int   g_rowptr[NROWS + 1];
__device__ int   g_cursor[NROWS];
__device__ int   g_srcg[ETOT];
__device__ float g_wg[ETOT];
__device__ int   g_bsums[512];
__device__ float g_wsum[2 * 4 * HID * HID];
__device__ float g_bsum[2 * 4 * HID];
__device__ __nv_bfloat16 g_wh[NWCHUNK * HID * HID];
__device__ __nv_bfloat16 g_wl[NWCHUNK * HID * HID];

// ---------------------------------------------------------------------------
// PTX helpers
// ---------------------------------------------------------------------------
#define LDSM4(R, addr)                                                          \
    asm volatile("ldmatrix.sync.aligned.m8n8.x4.shared.b16 {%0,%1,%2,%3}, [%4];" \
                 : "=r"((R)[0]), "=r"((R)[1]), "=r"((R)[2]), "=r"((R)[3])        \
                 : "r"(addr))

#define MMA16816(C, A, B0, B1)                                                  \
    asm volatile("mma.sync.aligned.m16n8k16.row.col.f32.bf16.bf16.f32 "         \
                 "{%0,%1,%2,%3},{%4,%5,%6,%7},{%8,%9},{%0,%1,%2,%3};"           \
                 : "+f"((C)[0]), "+f"((C)[1]), "+f"((C)[2]), "+f"((C)[3])        \
                 : "r"((A)[0]), "r"((A)[1]), "r"((A)[2]), "r"((A)[3]),           \
                   "r"(B0), "r"(B1))

__device__ __forceinline__ uint32_t pack_bf16(__nv_bfloat16 a, __nv_bfloat16 b)
{
    __nv_bfloat162 p = __halves2bfloat162(a, b);
    return *reinterpret_cast<uint32_t*>(&p);
}

__device__ __forceinline__ void split_pair(float x, float y, uint32_t& hi, uint32_t& lo)
{
    __nv_bfloat16 hx = __float2bfloat16(x);
    __nv_bfloat16 hy = __float2bfloat16(y);
    __nv_bfloat16 lx = __float2bfloat16(x - __bfloat162float(hx));
    __nv_bfloat16 ly = __float2bfloat16(y - __bfloat162float(hy));
    hi = pack_bf16(hx, hy);
    lo = pack_bf16(lx, ly);
}

// ---------------------------------------------------------------------------
// Multi-chunk tensor-core GEMM (bf16x3 split):
//   C = bias + A0 @ W0^T + sum_q Aq @ Wq^T
// NCH = number of K=128 chunks (template; fully unrolled, no runtime guard).
// Chunk 0: fp32 A0 (converted in-kernel). Chunks 1..NCH-1: pre-split bf16.
// All W chunks pre-split. Block tile 128x128, 8 warps (4m x 2n), occ 2.
// ---------------------------------------------------------------------------
struct GemmArgs {
    const float* A0f;
    const __nv_bfloat16 *A1h, *A1l, *A2h, *A2l, *A3h, *A3l;
    const __nv_bfloat16 *W0h, *W0l, *W1h, *W1l, *W2h, *W2l, *W3h, *W3l;
};

template <int NCH>
__global__ void __launch_bounds__(256, 2)
gemm_mma(GemmArgs p, const float* __restrict__ bias,
         float* __restrict__ C, int n, int dorelu)
{
    extern __shared__ __nv_bfloat16 smem[];
    uint32_t sb = (uint32_t)__cvta_generic_to_shared(smem);

    const int tid  = threadIdx.x;
    const int lane = tid & 31;
    const int warp = tid >> 5;
    const int wm = warp >> 1;
    const int wn = warp & 1;
    const int bm = blockIdx.x * 128;

    float c[2][8][4];
#pragma unroll
    for (int i = 0; i < 2; i++)
#pragma unroll
        for (int j = 0; j < 8; j++)
#pragma unroll
            for (int q = 0; q < 4; q++) c[i][j][q] = 0.f;

#pragma unroll
    for (int ch = 0; ch < NCH; ch++) {
        // compile-time pointer selection per unrolled iteration
        const __nv_bfloat16* Wh = (ch == 0) ? p.W0h : (ch == 1) ? p.W1h
                                : (ch == 2) ? p.W2h : p.W3h;
        const __nv_bfloat16* Wl = (ch == 0) ? p.W0l : (ch == 1) ? p.W1l
                                : (ch == 2) ? p.W2l : p.W3l;
        const __nv_bfloat16* Ahi = (ch == 1) ? p.A1h : (ch == 2) ? p.A2h : p.A3h;
        const __nv_bfloat16* Alo = (ch == 1) ? p.A1l : (ch == 2) ? p.A2l : p.A3l;

        for (int kb = 0; kb < 128; kb += 64) {
            // ---- A fill ----
            if (ch == 0) {
                // fp32 -> split-bf16 conversion path
#pragma unroll
                for (int it = 0; it < 8; it++) {
                    int idx = tid + it * 256;
                    int r   = idx >> 4;
                    int kc  = (idx & 15) << 2;
                    float4 va = make_float4(0.f, 0.f, 0.f, 0.f);
                    int row = bm + r;
                    if (row < n)
                        va = *(const float4*)(p.A0f + (size_t)row * HID + kb + kc);
                    uint32_t h01, l01, h23, l23;
                    split_pair(va.x, va.y, h01, l01);
                    split_pair(va.z, va.w, h23, l23);
                    size_t so = (size_t)r * LDS + kc;
                    *(uint2*)(smem + so)             = make_uint2(h01, h23);
                    *(uint2*)(smem + 128 * LDS + so) = make_uint2(l01, l23);
                }
            } else {
                // direct copy of pre-split bf16 (16B per load)
                const uint4 z = make_uint4(0, 0, 0, 0);
#pragma unroll
                for (int it = 0; it < 4; it++) {
                    int idx = tid + it * 256;          // 0..1023
                    int r   = idx >> 3;
                    int kc  = (idx & 7) << 3;
                    int row = bm + r;
                    size_t go = (size_t)row * HID + kb + kc;
                    size_t so = (size_t)r * LDS + kc;
                    uint4 vh = (row < n) ? *(const uint4*)(Ahi + go) : z;
                    uint4 vl = (row < n) ? *(const uint4*)(Alo + go) : z;
                    *(uint4*)(smem + so)             = vh;
                    *(uint4*)(smem + 128 * LDS + so) = vl;
                }
            }
            // ---- W fill (pre-split, direct copy) ----
#pragma unroll
            for (int it = 0; it < 4; it++) {
                int idx = tid + it * 256;
                int r   = idx >> 3;
                int kc  = (idx & 7) << 3;
                size_t go = (size_t)r * HID + kb + kc;
                size_t so = (size_t)r * LDS + kc;
                *(uint4*)(smem + 2 * 128 * LDS + so) = *(const uint4*)(Wh + go);
                *(uint4*)(smem + 3 * 128 * LDS + so) = *(const uint4*)(Wl + go);
            }
            __syncthreads();

            // ---- 4 k-steps of 16 ----
#pragma unroll
            for (int ks = 0; ks < 4; ks++) {
                uint32_t ah[2][4], al[2][4], bh[4][4], bl[4][4];
#pragma unroll
                for (int i = 0; i < 2; i++) {
                    int r   = wm * 32 + i * 16 + (lane & 15);
                    int kby = ks * 32 + ((lane >> 4) << 4);
                    uint32_t ad = sb + r * LDSB + kby;
                    LDSM4(ah[i], ad);
                    LDSM4(al[i], ad + TILE_B);
                }
#pragma unroll
                for (int pq = 0; pq < 4; pq++) {
                    int nr  = wn * 64 + (2 * pq + (lane >> 4)) * 8 + (lane & 7);
                    int kby = ks * 32 + ((lane >> 3) & 1) * 16;
                    uint32_t ad = sb + 2 * TILE_B + nr * LDSB + kby;
                    LDSM4(bh[pq], ad);
                    LDSM4(bl[pq], ad + TILE_B);
                }
#pragma unroll
                for (int i = 0; i < 2; i++)
#pragma unroll
                    for (int j = 0; j < 8; j++) {
                        const uint32_t* b = bh[j >> 1] + (j & 1) * 2;
                        MMA16816(c[i][j], ah[i], b[0], b[1]);
                    }
#pragma unroll
                for (int i = 0; i < 2; i++)
#pragma unroll
                    for (int j = 0; j < 8; j++) {
                        const uint32_t* b = bl[j >> 1] + (j & 1) * 2;
                        MMA16816(c[i][j], ah[i], b[0], b[1]);
                    }
#pragma unroll
                for (int i = 0; i < 2; i++)
#pragma unroll
                    for (int j = 0; j < 8; j++) {
                        const uint32_t* b = bh[j >> 1] + (j & 1) * 2;
                        MMA16816(c[i][j], al[i], b[0], b[1]);
                    }
            }
            __syncthreads();
        }
    }

    // ---- epilogue ----
    const int g  = lane >> 2;
    const int tq = lane & 3;
#pragma unroll
    for (int i = 0; i < 2; i++) {
#pragma unroll
        for (int half = 0; half < 2; half++) {
            int row = bm + wm * 32 + i * 16 + half * 8 + g;
            if (row >= n) continue;
#pragma unroll
            for (int j = 0; j < 8; j++) {
                int col = wn * 64 + j * 8 + tq * 2;
                float vx = c[i][j][half * 2 + 0] + bias[col];
                float vy = c[i][j][half * 2 + 1] + bias[col + 1];
                if (dorelu) {
                    vx = fmaxf(vx, 0.f);
                    vy = fmaxf(vy, 0.f);
                }
                *(float2*)(C + (size_t)row * HID + col) = make_float2(vx, vy);
            }
        }
    }
}

// ---------------------------------------------------------------------------
// CSR build: count -> scan -> fill (per relation, proven structure)
// ---------------------------------------------------------------------------
__global__ void count_kernel(const int* __restrict__ dst, int E, int* __restrict__ cnt)
{
    int e = blockIdx.x * blockDim.x + threadIdx.x;
    if (e < E) atomicAdd(&cnt[dst[e]], 1);
}

__global__ void scan1_kernel(const int* __restrict__ cnt, int* __restrict__ rowptr,
                             int* __restrict__ bsums, int n)
{
    __shared__ int wsums[8];
    int base = blockIdx.x * 4096 + threadIdx.x * 16;
    int v[16];
    int s = 0;
#pragma unroll
    for (int i = 0; i < 16; i++) {
        v[i] = (base + i < n) ? cnt[base + i] : 0;
        s += v[i];
    }
    int lane = threadIdx.x & 31, w = threadIdx.x >> 5;
    int ps = s;
#pragma unroll
    for (int o = 1; o < 32; o <<= 1) {
        int t = __shfl_up_sync(0xffffffffu, ps, o);
        if (lane >= o) ps += t;
    }
    if (lane == 31) wsums[w] = ps;
    __syncthreads();
    if (w == 0) {
        int t = (lane < 8) ? wsums[lane] : 0;
#pragma unroll
        for (int o = 1; o < 8; o <<= 1) {
            int u = __shfl_up_sync(0xffffffffu, t, o);
            if (lane >= o) t += u;
        }
        if (lane < 8) wsums[lane] = t;
    }
    __syncthreads();
    int excl = ps - s + (w ? wsums[w - 1] : 0);
    int run = excl;
#pragma unroll
    for (int i = 0; i < 16; i++) {
        if (base + i < n) rowptr[base + i] = run;
        run += v[i];
    }
    if (threadIdx.x == 0) bsums[blockIdx.x] = wsums[7];
}

__global__ void scan2_kernel(int* __restrict__ bsums, int nb)
{
    if (threadIdx.x == 0 && blockIdx.x == 0) {
        int run = 0;
        for (int i = 0; i < nb; i++) {
            int t = bsums[i];
            bsums[i] = run;
            run += t;
        }
    }
}

// scan3 also initializes cursor (saves the 3.2MB memcpy launch)
__global__ void scan3_kernel(int* __restrict__ rowptr, const int* __restrict__ bsums,
                             int* __restrict__ cursor, int n)
{
    int base = blockIdx.x * 4096 + threadIdx.x * 16;
    int off = bsums[blockIdx.x];
#pragma unroll
    for (int i = 0; i < 16; i++)
        if (base + i < n) {
            int v = rowptr[base + i] + off;
            rowptr[base + i] = v;
            cursor[base + i] = v;
        }
    if (blockIdx.x == 0 && threadIdx.x == 0) rowptr[n] = ETOT;
}

__global__ void fill_kernel(const int* __restrict__ src, const int* __restrict__ dst,
                            const float* __restrict__ ew, int E, int rowOff,
                            int* __restrict__ cursor,
                            int* __restrict__ srcg, float* __restrict__ wg)
{
    int e = blockIdx.x * blockDim.x + threadIdx.x;
    if (e >= E) return;
    int slot = atomicAdd(&cursor[rowOff + dst[e]], 1);
    srcg[slot] = src[e];
    wg[slot]   = ew[e];
}

// ---------------------------------------------------------------------------
// Combined Wl / bias per (layer, dst type).
// ---------------------------------------------------------------------------
__global__ void wsum_kernel(const float* __restrict__ W1l, const float* __restrict__ b1,
                            const float* __restrict__ W2l, const float* __restrict__ b2,
                            float* __restrict__ wsum, float* __restrict__ bsum)
{
    const int dstT[8] = {1, 0, 3, 0, 1, 3, 2, 1};
    int idx = blockIdx.x * blockDim.x + threadIdx.x;
    if (idx >= 2 * 4 * HID * HID) return;
    int l  = idx / (4 * HID * HID);
    int r  = idx % (4 * HID * HID);
    int d  = r / (HID * HID);
    int ij = r % (HID * HID);
    const float* W = l ? W2l : W1l;
    float s = 0.f;
#pragma unroll
    for (int t = 0; t < 8; t++)
        if (dstT[t] == d) s += W[t * HID * HID + ij];
    wsum[idx] = s;
    if (ij < HID) {
        const float* B = l ? b2 : b1;
        float sb = 0.f;
#pragma unroll
        for (int t = 0; t < 8; t++)
            if (dstT[t] == d) sb += B[t * HID + ij];
        bsum[(l * 4 + d) * HID + ij] = sb;
    }
}

// ---------------------------------------------------------------------------
// Pre-split all 24 weight chunks into bf16 hi/lo.
// ---------------------------------------------------------------------------
__global__ void wsplit_kernel(const float* __restrict__ wsum,
                              const float* __restrict__ W1r,
                              const float* __restrict__ W2r,
                              __nv_bfloat16* __restrict__ wh,
                              __nv_bfloat16* __restrict__ wl)
{
    int idx = blockIdx.x * blockDim.x + threadIdx.x;
    if (idx >= NWCHUNK * HID * HID) return;
    int c  = idx >> 14;
    int ij = idx & 16383;
    float v = (c < 8) ? wsum[idx]
            : (c < 16) ? W1r[(c - 8) * HID * HID + ij]
                       : W2r[(c - 16) * HID * HID + ij];
    __nv_bfloat16 h = __float2bfloat16(v);
    wh[idx] = h;
    wl[idx] = __float2bfloat16(v - __bfloat162float(h));
}

// ---------------------------------------------------------------------------
// CSR gather (per relation): one warp per dst row — no atomics.
// 4-edge unroll for MLP. Output written in split-bf16 form.
// ---------------------------------------------------------------------------
__global__ void gather_kernel(const float* __restrict__ x,
                              const int* __restrict__ rowptr,
                              const int* __restrict__ srcg,
                              const float* __restrict__ wg,
                              __nv_bfloat16* __restrict__ ahi,
                              __nv_bfloat16* __restrict__ alo,
                              int nrows, int rowOff)
{
    int row = (blockIdx.x * blockDim.x + threadIdx.x) >> 5;
    int lane = threadIdx.x & 31;
    if (row >= nrows) return;
    int g = rowOff + row;
    int e0 = rowptr[g], e1 = rowptr[g + 1];

    float4 acc = make_float4(0.f, 0.f, 0.f, 0.f);
    int e = e0;
    for (; e + 3 < e1; e += 4) {
        int   s0 = srcg[e],   s1 = srcg[e + 1], s2 = srcg[e + 2], s3 = srcg[e + 3];
        float w0 = wg[e],     w1 = wg[e + 1],   w2 = wg[e + 2],   w3 = wg[e + 3];
        float4 v0 = *((const float4*)(x + (size_t)s0 * HID) + lane);
        float4 v1 = *((const float4*)(x + (size_t)s1 * HID) + lane);
        float4 v2 = *((const float4*)(x + (size_t)s2 * HID) + lane);
        float4 v3 = *((const float4*)(x + (size_t)s3 * HID) + lane);
        acc.x += w0 * v0.x + w1 * v1.x + w2 * v2.x + w3 * v3.x;
        acc.y += w0 * v0.y + w1 * v1.y + w2 * v2.y + w3 * v3.y;
        acc.z += w0 * v0.z + w1 * v1.z + w2 * v2.z + w3 * v3.z;
        acc.w += w0 * v0.w + w1 * v1.w + w2 * v2.w + w3 * v3.w;
    }
    for (; e < e1; e++) {
        int s0 = srcg[e];
        float w0 = wg[e];
        float4 v0 = *((const float4*)(x + (size_t)s0 * HID) + lane);
        acc.x += w0 * v0.x;
        acc.y += w0 * v0.y;
        acc.z += w0 * v0.z;
        acc.w += w0 * v0.w;
    }
    float invd = 1.f / fmaxf((float)(e1 - e0), 1.f);
    acc.x *= invd; acc.y *= invd; acc.z *= invd; acc.w *= invd;

    uint32_t h01, l01, h23, l23;
    split_pair(acc.x, acc.y, h01, l01);
    split_pair(acc.z, acc.w, h23, l23);
    size_t off = (size_t)g * HID + lane * 4;
    *(uint2*)(ahi + off) = make_uint2(h01, h23);
    *(uint2*)(alo + off) = make_uint2(l01, l23);
}

// ---------------------------------------------------------------------------
// Host launch
// ---------------------------------------------------------------------------
struct Rel { int srcT, dstT, E, eiIdx, rev, ewIdx, rowOff; };

extern "C" void kernel_launch(void* const* d_in, const int* in_sizes, int n_in,
                              void* d_out, int out_size)
{
    (void)in_sizes; (void)n_in; (void)out_size;

    static const Rel rels[8] = {
        {0, 1, 500000, 18, 0, 10, 0},       // user -> product  (buys)
        {1, 0, 500000, 18, 1, 11, 100000},  // product -> user  (rev buys)
        {0, 3, 300000, 19, 0, 12, 300000},  // user -> query    (searches)
        {3, 0, 300000, 19, 1, 13, 350000},  // query -> user    (rev searches)
        {3, 1, 300000, 20, 0, 14, 550000},  // query -> product (matches)
        {1, 3, 300000, 20, 1, 15, 650000},  // product -> query (rev matches)
        {1, 2, 100000, 21, 0, 16, 700000},  // product -> category (in)
        {2, 1, 100000, 21, 1, 17, 702000},  // category -> product (rev in)
    };
    static const int relForDst[4][3] = { {1, 3, -1}, {0, 4, 7}, {6, -1, -1}, {2, 5, -1} };
    static const int nRelForDst[4]   = { 2, 3, 1, 2 };
    static const int    nodeN[4]   = {NU, NP, NC, NQ};
    static const size_t nodeOff[4] = {0, NU, NU + NP, NU + NP + NC};

    cudaFuncSetAttribute(gemm_mma<2>, cudaFuncAttributeMaxDynamicSharedMemorySize, SMEM_BYTES);
    cudaFuncSetAttribute(gemm_mma<3>, cudaFuncAttributeMaxDynamicSharedMemorySize, SMEM_BYTES);
    cudaFuncSetAttribute(gemm_mma<4>, cudaFuncAttributeMaxDynamicSharedMemorySize, SMEM_BYTES);

    float *hbuf, *wsum, *bsum, *wg;
    __nv_bfloat16 *ahi, *alo, *wh, *wl;
    int *cnt, *rowptr, *cursor, *srcg, *bsums;
    cudaGetSymbolAddress((void**)&ahi,    g_ahi);
    cudaGetSymbolAddress((void**)&alo,    g_alo);
    cudaGetSymbolAddress((void**)&hbuf,   g_h);
    cudaGetSymbolAddress((void**)&cnt,    g_cnt);
    cudaGetSymbolAddress((void**)&rowptr, g_rowptr);
    cudaGetSymbolAddress((void**)&cursor, g_cursor);
    cudaGetSymbolAddress((void**)&srcg,   g_srcg);
    cudaGetSymbolAddress((void**)&wg,     g_wg);
    cudaGetSymbolAddress((void**)&bsums,  g_bsums);
    cudaGetSymbolAddress((void**)&wsum,   g_wsum);
    cudaGetSymbolAddress((void**)&bsum,   g_bsum);
    cudaGetSymbolAddress((void**)&wh,     g_wh);
    cudaGetSymbolAddress((void**)&wl,     g_wl);

    const float* x0[4] = { (const float*)d_in[0], (const float*)d_in[1],
                           (const float*)d_in[2], (const float*)d_in[3] };
    const float* W1l = (const float*)d_in[4];
    const float* b1  = (const float*)d_in[5];
    const float* W1r = (const float*)d_in[6];
    const float* W2l = (const float*)d_in[7];
    const float* b2  = (const float*)d_in[8];
    const float* W2r = (const float*)d_in[9];
    float* out = (float*)d_out;

    cudaStream_t st = 0;
    const int NSCAN = (NROWS + 4095) / 4096;

    // ---- CSR build (layer-invariant) ----
    cudaMemsetAsync(cnt, 0, NROWS * sizeof(int), st);
    for (int t = 0; t < 8; t++) {
        const Rel& r = rels[t];
        const int* ei  = (const int*)d_in[r.eiIdx];
        const int* dst = r.rev ? ei : ei + r.E;
        count_kernel<<<(r.E + 255) / 256, 256, 0, st>>>(dst, r.E, cnt + r.rowOff);
    }
    scan1_kernel<<<NSCAN, 256, 0, st>>>(cnt, rowptr, bsums, NROWS);
    scan2_kernel<<<1, 32, 0, st>>>(bsums, NSCAN);
    scan3_kernel<<<NSCAN, 256, 0, st>>>(rowptr, bsums, cursor, NROWS);
    for (int t = 0; t < 8; t++) {
        const Rel& r = rels[t];
        const int* ei  = (const int*)d_in[r.eiIdx];
        const int* src = r.rev ? ei + r.E : ei;
        const int* dst = r.rev ? ei       : ei + r.E;
        const float* ew = (const float*)d_in[r.ewIdx];
        fill_kernel<<<(r.E + 255) / 256, 256, 0, st>>>(src, dst, ew, r.E, r.rowOff,
                                                       cursor, srcg, wg);
    }

    // ---- combined Wl / bias, pre-split weights ----
    wsum_kernel<<<(2 * 4 * HID * HID + 255) / 256, 256, 0, st>>>(W1l, b1, W2l, b2, wsum, bsum);
    wsplit_kernel<<<(NWCHUNK * HID * HID + 255) / 256, 256, 0, st>>>(wsum, W1r, W2r, wh, wl);

    // ---- two layers ----
    for (int layer = 0; layer < 2; layer++) {
        // gather raw features per relation (no atomics)
        for (int t = 0; t < 8; t++) {
            const Rel& r = rels[t];
            const float* x = layer ? (hbuf + nodeOff[r.srcT] * HID) : x0[r.srcT];
            int nrows = nodeN[r.dstT];
            gather_kernel<<<(nrows * 32 + 255) / 256, 256, 0, st>>>(
                x, rowptr, srcg, wg, ahi, alo, nrows, r.rowOff);
        }

        // one K-concat GEMM per dst type
        for (int d = 0; d < 4; d++) {
            const __nv_bfloat16 *Ah[3] = {nullptr, nullptr, nullptr};
            const __nv_bfloat16 *Al[3] = {nullptr, nullptr, nullptr};
            const __nv_bfloat16 *Whp[4] = {nullptr, nullptr, nullptr, nullptr};
            const __nv_bfloat16 *Wlp[4] = {nullptr, nullptr, nullptr, nullptr};
            Whp[0] = wh + (size_t)(layer * 4 + d) * HID * HID;
            Wlp[0] = wl + (size_t)(layer * 4 + d) * HID * HID;
            for (int q = 0; q < nRelForDst[d]; q++) {
                int t = relForDst[d][q];
                Ah[q] = ahi + (size_t)rels[t].rowOff * HID;
                Al[q] = alo + (size_t)rels[t].rowOff * HID;
                Whp[q + 1] = wh + (size_t)(8 + layer * 8 + t) * HID * HID;
                Wlp[q + 1] = wl + (size_t)(8 + layer * 8 + t) * HID * HID;
            }
            GemmArgs p;
            p.A0f = layer ? (hbuf + nodeOff[d] * HID) : x0[d];
            p.A1h = Ah[0]; p.A1l = Al[0];
            p.A2h = Ah[1]; p.A2l = Al[1];
            p.A3h = Ah[2]; p.A3l = Al[2];
            p.W0h = Whp[0]; p.W0l = Wlp[0];
            p.W1h = Whp[1]; p.W1l = Wlp[1];
            p.W2h = Whp[2]; p.W2l = Wlp[2];
            p.W3h = Whp[3]; p.W3l = Wlp[3];
            int nch = 1 + nRelForDst[d];
            float* C = layer ? (out + nodeOff[d] * HID) : (hbuf + nodeOff[d] * HID);
            if (nch == 2)
                gemm_mma<2><<<(nodeN[d] + 127) / 128, 256, SMEM_BYTES, st>>>(
                    p, bsum + (layer * 4 + d) * HID, C, nodeN[d], layer == 0 ? 1 : 0);
            else if (nch == 3)
                gemm_mma<3><<<(nodeN[d] + 127) / 128, 256, SMEM_BYTES, st>>>(
                    p, bsum + (layer * 4 + d) * HID, C, nodeN[d], layer == 0 ? 1 : 0);
            else
                gemm_mma<4><<<(nodeN[d] + 127) / 128, 256, SMEM_BYTES, st>>>(
                    p, bsum + (layer * 4 + d) * HID, C, nodeN[d], layer == 0 ? 1 : 0);
        }
    }
}

// round 12
// speedup vs baseline: 1.0762x; 1.0072x over previous
#include <cuda_runtime.h>
#include <cuda_bf16.h>
#include <stdint.h>

// ---------------------------------------------------------------------------
// HeteroGraphSAGE, 2 layers, 4 node types, 8 relations.
// agg[d] = Wr * (inv[d] * sum_e w_e * x[src])  -> CSR gather (no atomics) of
// RAW features, written in split-bf16 (hi+lo, produced anyway); one K-concat
// tensor-core GEMM per dst type, templated on NCH. Chunk 0 (x0/h) stays fp32,
// converted in-kernel (pre-splitting costs a 360MB pass: measured R7-R10).
// Gather uses 2-edge unroll (mean degree 3; 4-unroll regressed in R11).
// ---------------------------------------------------------------------------

#define NU 200000
#define NP 100000
#define NC 2000
#define NQ 50000
#define NTOT 352000
#define HID 128

#define NROWS 802000        // total (relation, dst-node) rows
#define ETOT  2400000       // total directed edges
#define NWCHUNK 24          // 8 wsum + 8 W1r + 8 W2r

#define LDS 72              // bf16 elems per smem row (64 data + 8 pad -> 144B stride)
#define LDSB 144
#define TILE_B (128 * LDSB)
#define SMEM_BYTES (4 * TILE_B)      // Ah, Al, Wh, Wl = 73728 B (occupancy 2)

// scratch (device globals; allocation-free)
__device__ __nv_bfloat16 g_ahi[(size_t)NROWS * HID];   // aggr hi
__device__ __nv_bfloat16 g_alo[(size_t)NROWS * HID];   // aggr lo
__device__ float g_h[(size_t)NTOT * HID];              // hidden after layer 1 (fp32)
__device__ int   g_cnt[NROWS];
__device__ int   g_rowptr[NROWS + 1];
__device__ int   g_cursor[NROWS];
__device__ int   g_srcg[ETOT];
__device__ float g_wg[ETOT];
__device__ int   g_bsums[512];
__device__ float g_wsum[2 * 4 * HID * HID];
__device__ float g_bsum[2 * 4 * HID];
__device__ __nv_bfloat16 g_wh[NWCHUNK * HID * HID];
__device__ __nv_bfloat16 g_wl[NWCHUNK * HID * HID];

// ---------------------------------------------------------------------------
// PTX helpers
// ---------------------------------------------------------------------------
#define LDSM4(R, addr)                                                          \
    asm volatile("ldmatrix.sync.aligned.m8n8.x4.shared.b16 {%0,%1,%2,%3}, [%4];" \
                 : "=r"((R)[0]), "=r"((R)[1]), "=r"((R)[2]), "=r"((R)[3])        \
                 : "r"(addr))

#define MMA16816(C, A, B0, B1)                                                  \
    asm volatile("mma.sync.aligned.m16n8k16.row.col.f32.bf16.bf16.f32 "         \
                 "{%0,%1,%2,%3},{%4,%5,%6,%7},{%8,%9},{%0,%1,%2,%3};"           \
                 : "+f"((C)[0]), "+f"((C)[1]), "+f"((C)[2]), "+f"((C)[3])        \
                 : "r"((A)[0]), "r"((A)[1]), "r"((A)[2]), "r"((A)[3]),           \
                   "r"(B0), "r"(B1))

__device__ __forceinline__ uint32_t pack_bf16(__nv_bfloat16 a, __nv_bfloat16 b)
{
    __nv_bfloat162 p = __halves2bfloat162(a, b);
    return *reinterpret_cast<uint32_t*>(&p);
}

__device__ __forceinline__ void split_pair(float x, float y, uint32_t& hi, uint32_t& lo)
{
    __nv_bfloat16 hx = __float2bfloat16(x);
    __nv_bfloat16 hy = __float2bfloat16(y);
    __nv_bfloat16 lx = __float2bfloat16(x - __bfloat162float(hx));
    __nv_bfloat16 ly = __float2bfloat16(y - __bfloat162float(hy));
    hi = pack_bf16(hx, hy);
    lo = pack_bf16(lx, ly);
}

// ---------------------------------------------------------------------------
// Multi-chunk tensor-core GEMM (bf16x3 split):
//   C = bias + A0 @ W0^T + sum_q Aq @ Wq^T
// NCH = number of K=128 chunks (template; fully unrolled, no runtime guard).
// Chunk 0: fp32 A0 (converted in-kernel). Chunks 1..NCH-1: pre-split bf16.
// All W chunks pre-split. Block tile 128x128, 8 warps (4m x 2n), occ 2.
// ---------------------------------------------------------------------------
struct GemmArgs {
    const float* A0f;
    const __nv_bfloat16 *A1h, *A1l, *A2h, *A2l, *A3h, *A3l;
    const __nv_bfloat16 *W0h, *W0l, *W1h, *W1l, *W2h, *W2l, *W3h, *W3l;
};

template <int NCH>
__global__ void __launch_bounds__(256, 2)
gemm_mma(GemmArgs p, const float* __restrict__ bias,
         float* __restrict__ C, int n, int dorelu)
{
    extern __shared__ __nv_bfloat16 smem[];
    uint32_t sb = (uint32_t)__cvta_generic_to_shared(smem);

    const int tid  = threadIdx.x;
    const int lane = tid & 31;
    const int warp = tid >> 5;
    const int wm = warp >> 1;
    const int wn = warp & 1;
    const int bm = blockIdx.x * 128;

    float c[2][8][4];
#pragma unroll
    for (int i = 0; i < 2; i++)
#pragma unroll
        for (int j = 0; j < 8; j++)
#pragma unroll
            for (int q = 0; q < 4; q++) c[i][j][q] = 0.f;

#pragma unroll
    for (int ch = 0; ch < NCH; ch++) {
        // compile-time pointer selection per unrolled iteration
        const __nv_bfloat16* Wh = (ch == 0) ? p.W0h : (ch == 1) ? p.W1h
                                : (ch == 2) ? p.W2h : p.W3h;
        const __nv_bfloat16* Wl = (ch == 0) ? p.W0l : (ch == 1) ? p.W1l
                                : (ch == 2) ? p.W2l : p.W3l;
        const __nv_bfloat16* Ahi = (ch == 1) ? p.A1h : (ch == 2) ? p.A2h : p.A3h;
        const __nv_bfloat16* Alo = (ch == 1) ? p.A1l : (ch == 2) ? p.A2l : p.A3l;

        for (int kb = 0; kb < 128; kb += 64) {
            // ---- A fill ----
            if (ch == 0) {
                // fp32 -> split-bf16 conversion path
#pragma unroll
                for (int it = 0; it < 8; it++) {
                    int idx = tid + it * 256;
                    int r   = idx >> 4;
                    int kc  = (idx & 15) << 2;
                    float4 va = make_float4(0.f, 0.f, 0.f, 0.f);
                    int row = bm + r;
                    if (row < n)
                        va = *(const float4*)(p.A0f + (size_t)row * HID + kb + kc);
                    uint32_t h01, l01, h23, l23;
                    split_pair(va.x, va.y, h01, l01);
                    split_pair(va.z, va.w, h23, l23);
                    size_t so = (size_t)r * LDS + kc;
                    *(uint2*)(smem + so)             = make_uint2(h01, h23);
                    *(uint2*)(smem + 128 * LDS + so) = make_uint2(l01, l23);
                }
            } else {
                // direct copy of pre-split bf16 (16B per load)
                const uint4 z = make_uint4(0, 0, 0, 0);
#pragma unroll
                for (int it = 0; it < 4; it++) {
                    int idx = tid + it * 256;          // 0..1023
                    int r   = idx >> 3;
                    int kc  = (idx & 7) << 3;
                    int row = bm + r;
                    size_t go = (size_t)row * HID + kb + kc;
                    size_t so = (size_t)r * LDS + kc;
                    uint4 vh = (row < n) ? *(const uint4*)(Ahi + go) : z;
                    uint4 vl = (row < n) ? *(const uint4*)(Alo + go) : z;
                    *(uint4*)(smem + so)             = vh;
                    *(uint4*)(smem + 128 * LDS + so) = vl;
                }
            }
            // ---- W fill (pre-split, direct copy) ----
#pragma unroll
            for (int it = 0; it < 4; it++) {
                int idx = tid + it * 256;
                int r   = idx >> 3;
                int kc  = (idx & 7) << 3;
                size_t go = (size_t)r * HID + kb + kc;
                size_t so = (size_t)r * LDS + kc;
                *(uint4*)(smem + 2 * 128 * LDS + so) = *(const uint4*)(Wh + go);
                *(uint4*)(smem + 3 * 128 * LDS + so) = *(const uint4*)(Wl + go);
            }
            __syncthreads();

            // ---- 4 k-steps of 16 ----
#pragma unroll
            for (int ks = 0; ks < 4; ks++) {
                uint32_t ah[2][4], al[2][4], bh[4][4], bl[4][4];
#pragma unroll
                for (int i = 0; i < 2; i++) {
                    int r   = wm * 32 + i * 16 + (lane & 15);
                    int kby = ks * 32 + ((lane >> 4) << 4);
                    uint32_t ad = sb + r * LDSB + kby;
                    LDSM4(ah[i], ad);
                    LDSM4(al[i], ad + TILE_B);
                }
#pragma unroll
                for (int pq = 0; pq < 4; pq++) {
                    int nr  = wn * 64 + (2 * pq + (lane >> 4)) * 8 + (lane & 7);
                    int kby = ks * 32 + ((lane >> 3) & 1) * 16;
                    uint32_t ad = sb + 2 * TILE_B + nr * LDSB + kby;
                    LDSM4(bh[pq], ad);
                    LDSM4(bl[pq], ad + TILE_B);
                }
#pragma unroll
                for (int i = 0; i < 2; i++)
#pragma unroll
                    for (int j = 0; j < 8; j++) {
                        const uint32_t* b = bh[j >> 1] + (j & 1) * 2;
                        MMA16816(c[i][j], ah[i], b[0], b[1]);
                    }
#pragma unroll
                for (int i = 0; i < 2; i++)
#pragma unroll
                    for (int j = 0; j < 8; j++) {
                        const uint32_t* b = bl[j >> 1] + (j & 1) * 2;
                        MMA16816(c[i][j], ah[i], b[0], b[1]);
                    }
#pragma unroll
                for (int i = 0; i < 2; i++)
#pragma unroll
                    for (int j = 0; j < 8; j++) {
                        const uint32_t* b = bh[j >> 1] + (j & 1) * 2;
                        MMA16816(c[i][j], al[i], b[0], b[1]);
                    }
            }
            __syncthreads();
        }
    }

    // ---- epilogue ----
    const int g  = lane >> 2;
    const int tq = lane & 3;
#pragma unroll
    for (int i = 0; i < 2; i++) {
#pragma unroll
        for (int half = 0; half < 2; half++) {
            int row = bm + wm * 32 + i * 16 + half * 8 + g;
            if (row >= n) continue;
#pragma unroll
            for (int j = 0; j < 8; j++) {
                int col = wn * 64 + j * 8 + tq * 2;
                float vx = c[i][j][half * 2 + 0] + bias[col];
                float vy = c[i][j][half * 2 + 1] + bias[col + 1];
                if (dorelu) {
                    vx = fmaxf(vx, 0.f);
                    vy = fmaxf(vy, 0.f);
                }
                *(float2*)(C + (size_t)row * HID + col) = make_float2(vx, vy);
            }
        }
    }
}

// ---------------------------------------------------------------------------
// merged CSR count over all 8 relations (one launch)
// ---------------------------------------------------------------------------
__global__ void csr_count(const int* __restrict__ eb, const int* __restrict__ es,
                          const int* __restrict__ em, const int* __restrict__ ein,
                          int* __restrict__ cnt)
{
    int e = blockIdx.x * 256 + threadIdx.x;
    if (e >= ETOT) return;
    const int* dstp; int rowOff, le;
    if      (e <  500000) { dstp = eb + 500000;  rowOff = 0;      le = e; }
    else if (e < 1000000) { dstp = eb;           rowOff = 100000; le = e - 500000; }
    else if (e < 1300000) { dstp = es + 300000;  rowOff = 300000; le = e - 1000000; }
    else if (e < 1600000) { dstp = es;           rowOff = 350000; le = e - 1300000; }
    else if (e < 1900000) { dstp = em + 300000;  rowOff = 550000; le = e - 1600000; }
    else if (e < 2200000) { dstp = em;           rowOff = 650000; le = e - 1900000; }
    else if (e < 2300000) { dstp = ein + 100000; rowOff = 700000; le = e - 2200000; }
    else                  { dstp = ein;          rowOff = 702000; le = e - 2300000; }
    atomicAdd(&cnt[rowOff + dstp[le]], 1);
}

__global__ void scan1_kernel(const int* __restrict__ cnt, int* __restrict__ rowptr,
                             int* __restrict__ bsums, int n)
{
    __shared__ int wsums[8];
    int base = blockIdx.x * 4096 + threadIdx.x * 16;
    int v[16];
    int s = 0;
#pragma unroll
    for (int i = 0; i < 16; i++) {
        v[i] = (base + i < n) ? cnt[base + i] : 0;
        s += v[i];
    }
    int lane = threadIdx.x & 31, w = threadIdx.x >> 5;
    int ps = s;
#pragma unroll
    for (int o = 1; o < 32; o <<= 1) {
        int t = __shfl_up_sync(0xffffffffu, ps, o);
        if (lane >= o) ps += t;
    }
    if (lane == 31) wsums[w] = ps;
    __syncthreads();
    if (w == 0) {
        int t = (lane < 8) ? wsums[lane] : 0;
#pragma unroll
        for (int o = 1; o < 8; o <<= 1) {
            int u = __shfl_up_sync(0xffffffffu, t, o);
            if (lane >= o) t += u;
        }
        if (lane < 8) wsums[lane] = t;
    }
    __syncthreads();
    int excl = ps - s + (w ? wsums[w - 1] : 0);
    int run = excl;
#pragma unroll
    for (int i = 0; i < 16; i++) {
        if (base + i < n) rowptr[base + i] = run;
        run += v[i];
    }
    if (threadIdx.x == 0) bsums[blockIdx.x] = wsums[7];
}

__global__ void scan2_kernel(int* __restrict__ bsums, int nb)
{
    if (threadIdx.x == 0 && blockIdx.x == 0) {
        int run = 0;
        for (int i = 0; i < nb; i++) {
            int t = bsums[i];
            bsums[i] = run;
            run += t;
        }
    }
}

// scan3 also initializes cursor (saves the 3.2MB memcpy launch)
__global__ void scan3_kernel(int* __restrict__ rowptr, const int* __restrict__ bsums,
                             int* __restrict__ cursor, int n)
{
    int base = blockIdx.x * 4096 + threadIdx.x * 16;
    int off = bsums[blockIdx.x];
#pragma unroll
    for (int i = 0; i < 16; i++)
        if (base + i < n) {
            int v = rowptr[base + i] + off;
            rowptr[base + i] = v;
            cursor[base + i] = v;
        }
    if (blockIdx.x == 0 && threadIdx.x == 0) rowptr[n] = ETOT;
}

// ---------------------------------------------------------------------------
// merged CSR fill over all 8 relations (one launch)
// ---------------------------------------------------------------------------
__global__ void csr_fill(const int* __restrict__ eb, const int* __restrict__ es,
                         const int* __restrict__ em, const int* __restrict__ ein,
                         const float* __restrict__ w0, const float* __restrict__ w1,
                         const float* __restrict__ w2, const float* __restrict__ w3,
                         const float* __restrict__ w4, const float* __restrict__ w5,
                         const float* __restrict__ w6, const float* __restrict__ w7,
                         int* __restrict__ cursor, int* __restrict__ srcg,
                         float* __restrict__ wg)
{
    int e = blockIdx.x * 256 + threadIdx.x;
    if (e >= ETOT) return;
    const int *dstp, *srcp; const float* ewp; int rowOff, le;
    if      (e <  500000) { dstp = eb + 500000;  srcp = eb;           ewp = w0; rowOff = 0;      le = e; }
    else if (e < 1000000) { dstp = eb;           srcp = eb + 500000;  ewp = w1; rowOff = 100000; le = e - 500000; }
    else if (e < 1300000) { dstp = es + 300000;  srcp = es;           ewp = w2; rowOff = 300000; le = e - 1000000; }
    else if (e < 1600000) { dstp = es;           srcp = es + 300000;  ewp = w3; rowOff = 350000; le = e - 1300000; }
    else if (e < 1900000) { dstp = em + 300000;  srcp = em;           ewp = w4; rowOff = 550000; le = e - 1600000; }
    else if (e < 2200000) { dstp = em;           srcp = em + 300000;  ewp = w5; rowOff = 650000; le = e - 1900000; }
    else if (e < 2300000) { dstp = ein + 100000; srcp = ein;          ewp = w6; rowOff = 700000; le = e - 2200000; }
    else                  { dstp = ein;          srcp = ein + 100000; ewp = w7; rowOff = 702000; le = e - 2300000; }
    int slot = atomicAdd(&cursor[rowOff + dstp[le]], 1);
    srcg[slot] = srcp[le];
    wg[slot]   = ewp[le];
}

// ---------------------------------------------------------------------------
// Combined Wl / bias per (layer, dst type).
// ---------------------------------------------------------------------------
__global__ void wsum_kernel(const float* __restrict__ W1l, const float* __restrict__ b1,
                            const float* __restrict__ W2l, const float* __restrict__ b2,
                            float* __restrict__ wsum, float* __restrict__ bsum)
{
    const int dstT[8] = {1, 0, 3, 0, 1, 3, 2, 1};
    int idx = blockIdx.x * blockDim.x + threadIdx.x;
    if (idx >= 2 * 4 * HID * HID) return;
    int l  = idx / (4 * HID * HID);
    int r  = idx % (4 * HID * HID);
    int d  = r / (HID * HID);
    int ij = r % (HID * HID);
    const float* W = l ? W2l : W1l;
    float s = 0.f;
#pragma unroll
    for (int t = 0; t < 8; t++)
        if (dstT[t] == d) s += W[t * HID * HID + ij];
    wsum[idx] = s;
    if (ij < HID) {
        const float* B = l ? b2 : b1;
        float sb = 0.f;
#pragma unroll
        for (int t = 0; t < 8; t++)
            if (dstT[t] == d) sb += B[t * HID + ij];
        bsum[(l * 4 + d) * HID + ij] = sb;
    }
}

// ---------------------------------------------------------------------------
// Pre-split all 24 weight chunks into bf16 hi/lo.
// ---------------------------------------------------------------------------
__global__ void wsplit_kernel(const float* __restrict__ wsum,
                              const float* __restrict__ W1r,
                              const float* __restrict__ W2r,
                              __nv_bfloat16* __restrict__ wh,
                              __nv_bfloat16* __restrict__ wl)
{
    int idx = blockIdx.x * blockDim.x + threadIdx.x;
    if (idx >= NWCHUNK * HID * HID) return;
    int c  = idx >> 14;
    int ij = idx & 16383;
    float v = (c < 8) ? wsum[idx]
            : (c < 16) ? W1r[(c - 8) * HID * HID + ij]
                       : W2r[(c - 16) * HID * HID + ij];
    __nv_bfloat16 h = __float2bfloat16(v);
    wh[idx] = h;
    wl[idx] = __float2bfloat16(v - __bfloat162float(h));
}

// ---------------------------------------------------------------------------
// CSR gather (per relation): one warp per dst row — no atomics.
// 2-edge unroll (matches mean degree 3). Output written in split-bf16 form.
// ---------------------------------------------------------------------------
__global__ void gather_kernel(const float* __restrict__ x,
                              const int* __restrict__ rowptr,
                              const int* __restrict__ srcg,
                              const float* __restrict__ wg,
                              __nv_bfloat16* __restrict__ ahi,
                              __nv_bfloat16* __restrict__ alo,
                              int nrows, int rowOff)
{
    int row = (blockIdx.x * blockDim.x + threadIdx.x) >> 5;
    int lane = threadIdx.x & 31;
    if (row >= nrows) return;
    int g = rowOff + row;
    int e0 = rowptr[g], e1 = rowptr[g + 1];

    float4 acc = make_float4(0.f, 0.f, 0.f, 0.f);
    int e = e0;
    for (; e + 1 < e1; e += 2) {
        int   s0 = srcg[e],   s1 = srcg[e + 1];
        float w0 = wg[e],     w1 = wg[e + 1];
        float4 v0 = *((const float4*)(x + (size_t)s0 * HID) + lane);
        float4 v1 = *((const float4*)(x + (size_t)s1 * HID) + lane);
        acc.x += w0 * v0.x + w1 * v1.x;
        acc.y += w0 * v0.y + w1 * v1.y;
        acc.z += w0 * v0.z + w1 * v1.z;
        acc.w += w0 * v0.w + w1 * v1.w;
    }
    if (e < e1) {
        int s0 = srcg[e];
        float w0 = wg[e];
        float4 v0 = *((const float4*)(x + (size_t)s0 * HID) + lane);
        acc.x += w0 * v0.x;
        acc.y += w0 * v0.y;
        acc.z += w0 * v0.z;
        acc.w += w0 * v0.w;
    }
    float invd = 1.f / fmaxf((float)(e1 - e0), 1.f);
    acc.x *= invd; acc.y *= invd; acc.z *= invd; acc.w *= invd;

    uint32_t h01, l01, h23, l23;
    split_pair(acc.x, acc.y, h01, l01);
    split_pair(acc.z, acc.w, h23, l23);
    size_t off = (size_t)g * HID + lane * 4;
    *(uint2*)(ahi + off) = make_uint2(h01, h23);
    *(uint2*)(alo + off) = make_uint2(l01, l23);
}

// ---------------------------------------------------------------------------
// Host launch
// ---------------------------------------------------------------------------
struct Rel { int srcT, dstT, E, eiIdx, rev, ewIdx, rowOff; };

extern "C" void kernel_launch(void* const* d_in, const int* in_sizes, int n_in,
                              void* d_out, int out_size)
{
    (void)in_sizes; (void)n_in; (void)out_size;

    static const Rel rels[8] = {
        {0, 1, 500000, 18, 0, 10, 0},       // user -> product  (buys)
        {1, 0, 500000, 18, 1, 11, 100000},  // product -> user  (rev buys)
        {0, 3, 300000, 19, 0, 12, 300000},  // user -> query    (searches)
        {3, 0, 300000, 19, 1, 13, 350000},  // query -> user    (rev searches)
        {3, 1, 300000, 20, 0, 14, 550000},  // query -> product (matches)
        {1, 3, 300000, 20, 1, 15, 650000},  // product -> query (rev matches)
        {1, 2, 100000, 21, 0, 16, 700000},  // product -> category (in)
        {2, 1, 100000, 21, 1, 17, 702000},  // category -> product (rev in)
    };
    static const int relForDst[4][3] = { {1, 3, -1}, {0, 4, 7}, {6, -1, -1}, {2, 5, -1} };
    static const int nRelForDst[4]   = { 2, 3, 1, 2 };
    static const int    nodeN[4]   = {NU, NP, NC, NQ};
    static const size_t nodeOff[4] = {0, NU, NU + NP, NU + NP + NC};

    cudaFuncSetAttribute(gemm_mma<2>, cudaFuncAttributeMaxDynamicSharedMemorySize, SMEM_BYTES);
    cudaFuncSetAttribute(gemm_mma<3>, cudaFuncAttributeMaxDynamicSharedMemorySize, SMEM_BYTES);
    cudaFuncSetAttribute(gemm_mma<4>, cudaFuncAttributeMaxDynamicSharedMemorySize, SMEM_BYTES);

    float *hbuf, *wsum, *bsum, *wg;
    __nv_bfloat16 *ahi, *alo, *wh, *wl;
    int *cnt, *rowptr, *cursor, *srcg, *bsums;
    cudaGetSymbolAddress((void**)&ahi,    g_ahi);
    cudaGetSymbolAddress((void**)&alo,    g_alo);
    cudaGetSymbolAddress((void**)&hbuf,   g_h);
    cudaGetSymbolAddress((void**)&cnt,    g_cnt);
    cudaGetSymbolAddress((void**)&rowptr, g_rowptr);
    cudaGetSymbolAddress((void**)&cursor, g_cursor);
    cudaGetSymbolAddress((void**)&srcg,   g_srcg);
    cudaGetSymbolAddress((void**)&wg,     g_wg);
    cudaGetSymbolAddress((void**)&bsums,  g_bsums);
    cudaGetSymbolAddress((void**)&wsum,   g_wsum);
    cudaGetSymbolAddress((void**)&bsum,   g_bsum);
    cudaGetSymbolAddress((void**)&wh,     g_wh);
    cudaGetSymbolAddress((void**)&wl,     g_wl);

    const float* x0[4] = { (const float*)d_in[0], (const float*)d_in[1],
                           (const float*)d_in[2], (const float*)d_in[3] };
    const float* W1l = (const float*)d_in[4];
    const float* b1  = (const float*)d_in[5];
    const float* W1r = (const float*)d_in[6];
    const float* W2l = (const float*)d_in[7];
    const float* b2  = (const float*)d_in[8];
    const float* W2r = (const float*)d_in[9];
    const int* eb  = (const int*)d_in[18];
    const int* es  = (const int*)d_in[19];
    const int* em  = (const int*)d_in[20];
    const int* ein = (const int*)d_in[21];
    float* out = (float*)d_out;

    cudaStream_t st = 0;
    const int NSCAN = (NROWS + 4095) / 4096;

    // ---- CSR build (layer-invariant) ----
    cudaMemsetAsync(cnt, 0, NROWS * sizeof(int), st);
    csr_count<<<(ETOT + 255) / 256, 256, 0, st>>>(eb, es, em, ein, cnt);
    scan1_kernel<<<NSCAN, 256, 0, st>>>(cnt, rowptr, bsums, NROWS);
    scan2_kernel<<<1, 32, 0, st>>>(bsums, NSCAN);
    scan3_kernel<<<NSCAN, 256, 0, st>>>(rowptr, bsums, cursor, NROWS);
    csr_fill<<<(ETOT + 255) / 256, 256, 0, st>>>(
        eb, es, em, ein,
        (const float*)d_in[10], (const float*)d_in[11], (const float*)d_in[12],
        (const float*)d_in[13], (const float*)d_in[14], (const float*)d_in[15],
        (const float*)d_in[16], (const float*)d_in[17],
        cursor, srcg, wg);

    // ---- combined Wl / bias, pre-split weights ----
    wsum_kernel<<<(2 * 4 * HID * HID + 255) / 256, 256, 0, st>>>(W1l, b1, W2l, b2, wsum, bsum);
    wsplit_kernel<<<(NWCHUNK * HID * HID + 255) / 256, 256, 0, st>>>(wsum, W1r, W2r, wh, wl);

    // ---- two layers ----
    for (int layer = 0; layer < 2; layer++) {
        // gather raw features per relation (no atomics)
        for (int t = 0; t < 8; t++) {
            const Rel& r = rels[t];
            const float* x = layer ? (hbuf + nodeOff[r.srcT] * HID) : x0[r.srcT];
            int nrows = nodeN[r.dstT];
            gather_kernel<<<(nrows * 32 + 255) / 256, 256, 0, st>>>(
                x, rowptr, srcg, wg, ahi, alo, nrows, r.rowOff);
        }

        // one K-concat GEMM per dst type
        for (int d = 0; d < 4; d++) {
            const __nv_bfloat16 *Ah[3] = {nullptr, nullptr, nullptr};
            const __nv_bfloat16 *Al[3] = {nullptr, nullptr, nullptr};
            const __nv_bfloat16 *Whp[4] = {nullptr, nullptr, nullptr, nullptr};
            const __nv_bfloat16 *Wlp[4] = {nullptr, nullptr, nullptr, nullptr};
            Whp[0] = wh + (size_t)(layer * 4 + d) * HID * HID;
            Wlp[0] = wl + (size_t)(layer * 4 + d) * HID * HID;
            for (int q = 0; q < nRelForDst[d]; q++) {
                int t = relForDst[d][q];
                Ah[q] = ahi + (size_t)rels[t].rowOff * HID;
                Al[q] = alo + (size_t)rels[t].rowOff * HID;
                Whp[q + 1] = wh + (size_t)(8 + layer * 8 + t) * HID * HID;
                Wlp[q + 1] = wl + (size_t)(8 + layer * 8 + t) * HID * HID;
            }
            GemmArgs p;
            p.A0f = layer ? (hbuf + nodeOff[d] * HID) : x0[d];
            p.A1h = Ah[0]; p.A1l = Al[0];
            p.A2h = Ah[1]; p.A2l = Al[1];
            p.A3h = Ah[2]; p.A3l = Al[2];
            p.W0h = Whp[0]; p.W0l = Wlp[0];
            p.W1h = Whp[1]; p.W1l = Wlp[1];
            p.W2h = Whp[2]; p.W2l = Wlp[2];
            p.W3h = Whp[3]; p.W3l = Wlp[3];
            int nch = 1 + nRelForDst[d];
            float* C = layer ? (out + nodeOff[d] * HID) : (hbuf + nodeOff[d] * HID);
            if (nch == 2)
                gemm_mma<2><<<(nodeN[d] + 127) / 128, 256, SMEM_BYTES, st>>>(
                    p, bsum + (layer * 4 + d) * HID, C, nodeN[d], layer == 0 ? 1 : 0);
            else if (nch == 3)
                gemm_mma<3><<<(nodeN[d] + 127) / 128, 256, SMEM_BYTES, st>>>(
                    p, bsum + (layer * 4 + d) * HID, C, nodeN[d], layer == 0 ? 1 : 0);
            else
                gemm_mma<4><<<(nodeN[d] + 127) / 128, 256, SMEM_BYTES, st>>>(
                    p, bsum + (layer * 4 + d) * HID, C, nodeN[d], layer == 0 ? 1 : 0);
        }
    }
}

// round 13
// speedup vs baseline: 1.2894x; 1.1980x over previous
#include <cuda_runtime.h>
#include <cuda_fp16.h>
#include <stdint.h>

// ---------------------------------------------------------------------------
// HeteroGraphSAGE, 2 layers, 4 node types, 8 relations.  fp16 data plane:
// x0/h/aggr stored fp16 (node tables = 90MB -> L2-resident for the 4.8M
// random row gathers). GEMM = fp16 x (fp16-hi + fp16-lo W) -> 2 MMA passes,
// W error ~2^-23, A error 2^-12 -> total rel err ~3e-4 (threshold 1e-3).
// agg[d] = Wr * (inv[d] * sum_e w_e * x[src]) -> CSR gather (no atomics);
// one K-concat GEMM per dst type (template NCH).
// ---------------------------------------------------------------------------

#define NU 200000
#define NP 100000
#define NC 2000
#define NQ 50000
#define NTOT 352000
#define HID 128

#define NROWS 802000
#define ETOT  2400000
#define NWCHUNK 24

#define LDS 72              // fp16 elems per smem row (64 data + 8 pad -> 144B)
#define LDSB 144
#define TILE_B (128 * LDSB)          // 18432 B
#define SMEM_BYTES (3 * TILE_B)      // A, Wh, Wl = 55296 B (occupancy 2)

// device globals (allocation-free scratch)
__device__ __half g_x16[(size_t)NTOT * HID];   // x0 in fp16 (concatenated)
__device__ __half g_h16[(size_t)NTOT * HID];   // hidden in fp16
__device__ __half g_a16[(size_t)NROWS * HID];  // aggr in fp16
__device__ int    g_cnt[NROWS];
__device__ int    g_rowptr[NROWS + 1];
__device__ int    g_cursor[NROWS];
__device__ int    g_srcg[ETOT];
__device__ float  g_wg[ETOT];
__device__ int    g_bsums[512];
__device__ float  g_wsum[2 * 4 * HID * HID];
__device__ float  g_bsum[2 * 4 * HID];
__device__ __half g_wh[NWCHUNK * HID * HID];   // weights fp16 hi
__device__ __half g_wl[NWCHUNK * HID * HID];   // weights fp16 residual

// ---------------------------------------------------------------------------
// PTX helpers
// ---------------------------------------------------------------------------
#define LDSM4(R, addr)                                                          \
    asm volatile("ldmatrix.sync.aligned.m8n8.x4.shared.b16 {%0,%1,%2,%3}, [%4];" \
                 : "=r"((R)[0]), "=r"((R)[1]), "=r"((R)[2]), "=r"((R)[3])        \
                 : "r"(addr))

#define MMAF16(C, A, B0, B1)                                                    \
    asm volatile("mma.sync.aligned.m16n8k16.row.col.f32.f16.f16.f32 "           \
                 "{%0,%1,%2,%3},{%4,%5,%6,%7},{%8,%9},{%0,%1,%2,%3};"           \
                 : "+f"((C)[0]), "+f"((C)[1]), "+f"((C)[2]), "+f"((C)[3])        \
                 : "r"((A)[0]), "r"((A)[1]), "r"((A)[2]), "r"((A)[3]),           \
                   "r"(B0), "r"(B1))

__device__ __forceinline__ uint32_t pack_h2(__half a, __half b)
{
    __half2 p = __halves2half2(a, b);
    return *reinterpret_cast<uint32_t*>(&p);
}

// ---------------------------------------------------------------------------
// Multi-chunk fp16 tensor-core GEMM (W split hi+lo, 2 passes):
//   C = bias + sum_ch A_ch @ (Wh_ch + Wl_ch)^T
// NCH = chunks (template). L0=1: relu + write fp16 h; L0=0: write fp32 out.
// Block tile 128x128, 8 warps (4m x 2n), occ 2.
// ---------------------------------------------------------------------------
struct GemmArgs {
    const __half *A0, *A1, *A2, *A3;
    const __half *W0h, *W0l, *W1h, *W1l, *W2h, *W2l, *W3h, *W3l;
};

template <int NCH, int L0>
__global__ void __launch_bounds__(256, 2)
gemm_mma(GemmArgs p, const float* __restrict__ bias,
         float* __restrict__ C32, __half* __restrict__ C16, int n)
{
    extern __shared__ __half smem[];
    uint32_t sb = (uint32_t)__cvta_generic_to_shared(smem);

    const int tid  = threadIdx.x;
    const int lane = tid & 31;
    const int warp = tid >> 5;
    const int wm = warp >> 1;
    const int wn = warp & 1;
    const int bm = blockIdx.x * 128;

    float c[2][8][4];
#pragma unroll
    for (int i = 0; i < 2; i++)
#pragma unroll
        for (int j = 0; j < 8; j++)
#pragma unroll
            for (int q = 0; q < 4; q++) c[i][j][q] = 0.f;

#pragma unroll
    for (int ch = 0; ch < NCH; ch++) {
        const __half* A  = (ch == 0) ? p.A0  : (ch == 1) ? p.A1  : (ch == 2) ? p.A2  : p.A3;
        const __half* Wh = (ch == 0) ? p.W0h : (ch == 1) ? p.W1h : (ch == 2) ? p.W2h : p.W3h;
        const __half* Wl = (ch == 0) ? p.W0l : (ch == 1) ? p.W1l : (ch == 2) ? p.W2l : p.W3l;

        for (int kb = 0; kb < 128; kb += 64) {
            // ---- fills: pure 16B copies ----
            const uint4 z = make_uint4(0, 0, 0, 0);
#pragma unroll
            for (int it = 0; it < 4; it++) {
                int idx = tid + it * 256;          // granule 0..1023
                int r   = idx >> 3;                // row 0..127
                int kc  = (idx & 7) << 3;          // 8 halves = 16B
                int row = bm + r;
                size_t ga = (size_t)row * HID + kb + kc;
                size_t gw = (size_t)r * HID + kb + kc;
                size_t so = (size_t)r * LDS + kc;
                *(uint4*)(smem + so) = (row < n) ? *(const uint4*)(A + ga) : z;
                *(uint4*)(smem + 128 * LDS + so)     = *(const uint4*)(Wh + gw);
                *(uint4*)(smem + 2 * 128 * LDS + so) = *(const uint4*)(Wl + gw);
            }
            __syncthreads();

            // ---- 4 k-steps of 16, 2 MMA passes ----
#pragma unroll
            for (int ks = 0; ks < 4; ks++) {
                uint32_t a[2][4], bh[4][4], bl[4][4];
#pragma unroll
                for (int i = 0; i < 2; i++) {
                    int r   = wm * 32 + i * 16 + (lane & 15);
                    int kby = ks * 32 + ((lane >> 4) << 4);
                    LDSM4(a[i], sb + r * LDSB + kby);
                }
#pragma unroll
                for (int pq = 0; pq < 4; pq++) {
                    int nr  = wn * 64 + (2 * pq + (lane >> 4)) * 8 + (lane & 7);
                    int kby = ks * 32 + ((lane >> 3) & 1) * 16;
                    uint32_t ad = sb + TILE_B + nr * LDSB + kby;
                    LDSM4(bh[pq], ad);
                    LDSM4(bl[pq], ad + TILE_B);
                }
#pragma unroll
                for (int i = 0; i < 2; i++)
#pragma unroll
                    for (int j = 0; j < 8; j++) {
                        const uint32_t* b = bh[j >> 1] + (j & 1) * 2;
                        MMAF16(c[i][j], a[i], b[0], b[1]);
                    }
#pragma unroll
                for (int i = 0; i < 2; i++)
#pragma unroll
                    for (int j = 0; j < 8; j++) {
                        const uint32_t* b = bl[j >> 1] + (j & 1) * 2;
                        MMAF16(c[i][j], a[i], b[0], b[1]);
                    }
            }
            __syncthreads();
        }
    }

    // ---- epilogue ----
    const int g  = lane >> 2;
    const int tq = lane & 3;
#pragma unroll
    for (int i = 0; i < 2; i++) {
#pragma unroll
        for (int half = 0; half < 2; half++) {
            int row = bm + wm * 32 + i * 16 + half * 8 + g;
            if (row >= n) continue;
#pragma unroll
            for (int j = 0; j < 8; j++) {
                int col = wn * 64 + j * 8 + tq * 2;
                float vx = c[i][j][half * 2 + 0] + bias[col];
                float vy = c[i][j][half * 2 + 1] + bias[col + 1];
                if (L0) {
                    vx = fmaxf(vx, 0.f);
                    vy = fmaxf(vy, 0.f);
                    *(uint32_t*)(C16 + (size_t)row * HID + col) =
                        pack_h2(__float2half(vx), __float2half(vy));
                } else {
                    *(float2*)(C32 + (size_t)row * HID + col) = make_float2(vx, vy);
                }
            }
        }
    }
}

// ---------------------------------------------------------------------------
// merged CSR count (one launch)
// ---------------------------------------------------------------------------
__global__ void csr_count(const int* __restrict__ eb, const int* __restrict__ es,
                          const int* __restrict__ em, const int* __restrict__ ein,
                          int* __restrict__ cnt)
{
    int e = blockIdx.x * 256 + threadIdx.x;
    if (e >= ETOT) return;
    const int* dstp; int rowOff, le;
    if      (e <  500000) { dstp = eb + 500000;  rowOff = 0;      le = e; }
    else if (e < 1000000) { dstp = eb;           rowOff = 100000; le = e - 500000; }
    else if (e < 1300000) { dstp = es + 300000;  rowOff = 300000; le = e - 1000000; }
    else if (e < 1600000) { dstp = es;           rowOff = 350000; le = e - 1300000; }
    else if (e < 1900000) { dstp = em + 300000;  rowOff = 550000; le = e - 1600000; }
    else if (e < 2200000) { dstp = em;           rowOff = 650000; le = e - 1900000; }
    else if (e < 2300000) { dstp = ein + 100000; rowOff = 700000; le = e - 2200000; }
    else                  { dstp = ein;          rowOff = 702000; le = e - 2300000; }
    atomicAdd(&cnt[rowOff + dstp[le]], 1);
}

__global__ void scan1_kernel(const int* __restrict__ cnt, int* __restrict__ rowptr,
                             int* __restrict__ bsums, int n)
{
    __shared__ int wsums[8];
    int base = blockIdx.x * 4096 + threadIdx.x * 16;
    int v[16];
    int s = 0;
#pragma unroll
    for (int i = 0; i < 16; i++) {
        v[i] = (base + i < n) ? cnt[base + i] : 0;
        s += v[i];
    }
    int lane = threadIdx.x & 31, w = threadIdx.x >> 5;
    int ps = s;
#pragma unroll
    for (int o = 1; o < 32; o <<= 1) {
        int t = __shfl_up_sync(0xffffffffu, ps, o);
        if (lane >= o) ps += t;
    }
    if (lane == 31) wsums[w] = ps;
    __syncthreads();
    if (w == 0) {
        int t = (lane < 8) ? wsums[lane] : 0;
#pragma unroll
        for (int o = 1; o < 8; o <<= 1) {
            int u = __shfl_up_sync(0xffffffffu, t, o);
            if (lane >= o) t += u;
        }
        if (lane < 8) wsums[lane] = t;
    }
    __syncthreads();
    int excl = ps - s + (w ? wsums[w - 1] : 0);
    int run = excl;
#pragma unroll
    for (int i = 0; i < 16; i++) {
        if (base + i < n) rowptr[base + i] = run;
        run += v[i];
    }
    if (threadIdx.x == 0) bsums[blockIdx.x] = wsums[7];
}

__global__ void scan2_kernel(int* __restrict__ bsums, int nb)
{
    if (threadIdx.x == 0 && blockIdx.x == 0) {
        int run = 0;
        for (int i = 0; i < nb; i++) {
            int t = bsums[i];
            bsums[i] = run;
            run += t;
        }
    }
}

__global__ void scan3_kernel(int* __restrict__ rowptr, const int* __restrict__ bsums,
                             int* __restrict__ cursor, int n)
{
    int base = blockIdx.x * 4096 + threadIdx.x * 16;
    int off = bsums[blockIdx.x];
#pragma unroll
    for (int i = 0; i < 16; i++)
        if (base + i < n) {
            int v = rowptr[base + i] + off;
            rowptr[base + i] = v;
            cursor[base + i] = v;
        }
    if (blockIdx.x == 0 && threadIdx.x == 0) rowptr[n] = ETOT;
}

// ---------------------------------------------------------------------------
// merged CSR fill (one launch)
// ---------------------------------------------------------------------------
__global__ void csr_fill(const int* __restrict__ eb, const int* __restrict__ es,
                         const int* __restrict__ em, const int* __restrict__ ein,
                         const float* __restrict__ w0, const float* __restrict__ w1,
                         const float* __restrict__ w2, const float* __restrict__ w3,
                         const float* __restrict__ w4, const float* __restrict__ w5,
                         const float* __restrict__ w6, const float* __restrict__ w7,
                         int* __restrict__ cursor, int* __restrict__ srcg,
                         float* __restrict__ wg)
{
    int e = blockIdx.x * 256 + threadIdx.x;
    if (e >= ETOT) return;
    const int *dstp, *srcp; const float* ewp; int rowOff, le;
    if      (e <  500000) { dstp = eb + 500000;  srcp = eb;           ewp = w0; rowOff = 0;      le = e; }
    else if (e < 1000000) { dstp = eb;           srcp = eb + 500000;  ewp = w1; rowOff = 100000; le = e - 500000; }
    else if (e < 1300000) { dstp = es + 300000;  srcp = es;           ewp = w2; rowOff = 300000; le = e - 1000000; }
    else if (e < 1600000) { dstp = es;           srcp = es + 300000;  ewp = w3; rowOff = 350000; le = e - 1300000; }
    else if (e < 1900000) { dstp = em + 300000;  srcp = em;           ewp = w4; rowOff = 550000; le = e - 1600000; }
    else if (e < 2200000) { dstp = em;           srcp = em + 300000;  ewp = w5; rowOff = 650000; le = e - 1900000; }
    else if (e < 2300000) { dstp = ein + 100000; srcp = ein;          ewp = w6; rowOff = 700000; le = e - 2200000; }
    else                  { dstp = ein;          srcp = ein + 100000; ewp = w7; rowOff = 702000; le = e - 2300000; }
    int slot = atomicAdd(&cursor[rowOff + dstp[le]], 1);
    srcg[slot] = srcp[le];
    wg[slot]   = ewp[le];
}

// ---------------------------------------------------------------------------
// Combined Wl / bias per (layer, dst type).
// ---------------------------------------------------------------------------
__global__ void wsum_kernel(const float* __restrict__ W1l, const float* __restrict__ b1,
                            const float* __restrict__ W2l, const float* __restrict__ b2,
                            float* __restrict__ wsum, float* __restrict__ bsum)
{
    const int dstT[8] = {1, 0, 3, 0, 1, 3, 2, 1};
    int idx = blockIdx.x * blockDim.x + threadIdx.x;
    if (idx >= 2 * 4 * HID * HID) return;
    int l  = idx / (4 * HID * HID);
    int r  = idx % (4 * HID * HID);
    int d  = r / (HID * HID);
    int ij = r % (HID * HID);
    const float* W = l ? W2l : W1l;
    float s = 0.f;
#pragma unroll
    for (int t = 0; t < 8; t++)
        if (dstT[t] == d) s += W[t * HID * HID + ij];
    wsum[idx] = s;
    if (ij < HID) {
        const float* B = l ? b2 : b1;
        float sb = 0.f;
#pragma unroll
        for (int t = 0; t < 8; t++)
            if (dstT[t] == d) sb += B[t * HID + ij];
        bsum[(l * 4 + d) * HID + ij] = sb;
    }
}

// ---------------------------------------------------------------------------
// Pre-split all 24 weight chunks into fp16 hi + fp16 residual.
// ---------------------------------------------------------------------------
__global__ void wsplit_kernel(const float* __restrict__ wsum,
                              const float* __restrict__ W1r,
                              const float* __restrict__ W2r,
                              __half* __restrict__ wh, __half* __restrict__ wl)
{
    int idx = blockIdx.x * blockDim.x + threadIdx.x;
    if (idx >= NWCHUNK * HID * HID) return;
    int c  = idx >> 14;
    int ij = idx & 16383;
    float v = (c < 8) ? wsum[idx]
            : (c < 16) ? W1r[(c - 8) * HID * HID + ij]
                       : W2r[(c - 16) * HID * HID + ij];
    __half h = __float2half(v);
    wh[idx] = h;
    wl[idx] = __float2half(v - __half2float(h));
}

// ---------------------------------------------------------------------------
// Convert x0 tables -> concatenated fp16 buffer (once per launch).
// ---------------------------------------------------------------------------
__global__ void xhalf_kernel(const float* __restrict__ xu, const float* __restrict__ xp,
                             const float* __restrict__ xc, const float* __restrict__ xq,
                             __half* __restrict__ x16)
{
    int i = blockIdx.x * 256 + threadIdx.x;          // 8-elem group index
    if (i >= NTOT * 16) return;
    int row = i >> 4;
    int c8  = (i & 15) << 3;
    const float* x;
    int lrow;
    if      (row < NU)           { x = xu; lrow = row; }
    else if (row < NU + NP)      { x = xp; lrow = row - NU; }
    else if (row < NU + NP + NC) { x = xc; lrow = row - NU - NP; }
    else                         { x = xq; lrow = row - NU - NP - NC; }
    float4 v0 = *(const float4*)(x + (size_t)lrow * HID + c8);
    float4 v1 = *(const float4*)(x + (size_t)lrow * HID + c8 + 4);
    uint4 o;
    o.x = pack_h2(__float2half(v0.x), __float2half(v0.y));
    o.y = pack_h2(__float2half(v0.z), __float2half(v0.w));
    o.z = pack_h2(__float2half(v1.x), __float2half(v1.y));
    o.w = pack_h2(__float2half(v1.z), __float2half(v1.w));
    *(uint4*)(x16 + (size_t)row * HID + c8) = o;
}

// ---------------------------------------------------------------------------
// Merged CSR gather: one warp per (relation,dst) row over ALL rows.
// Reads fp16 source (x16 or h16, concatenated); accumulates fp32;
// writes aggr fp16. 2-edge unroll.
// ---------------------------------------------------------------------------
__global__ void gather_kernel(const __half* __restrict__ xbase,
                              const int* __restrict__ rowptr,
                              const int* __restrict__ srcg,
                              const float* __restrict__ wg,
                              __half* __restrict__ a16)
{
    int row = (blockIdx.x * blockDim.x + threadIdx.x) >> 5;
    int lane = threadIdx.x & 31;
    if (row >= NROWS) return;
    const size_t OU = 0, OP = (size_t)NU * HID, OC = (size_t)(NU + NP) * HID,
                 OQ = (size_t)(NU + NP + NC) * HID;
    size_t xo = (row <  100000) ? OU
              : (row <  300000) ? OP
              : (row <  350000) ? OU
              : (row <  550000) ? OQ
              : (row <  650000) ? OQ
              : (row <  702000) ? OP : OC;
    const __half* x = xbase + xo;

    int e0 = rowptr[row], e1 = rowptr[row + 1];
    float4 acc = make_float4(0.f, 0.f, 0.f, 0.f);
    int e = e0;
    for (; e + 1 < e1; e += 2) {
        int   s0 = srcg[e],  s1 = srcg[e + 1];
        float w0 = wg[e],    w1 = wg[e + 1];
        uint2 u0 = *((const uint2*)(x + (size_t)s0 * HID) + lane);
        uint2 u1 = *((const uint2*)(x + (size_t)s1 * HID) + lane);
        float2 a0 = __half22float2(*reinterpret_cast<__half2*>(&u0.x));
        float2 b0 = __half22float2(*reinterpret_cast<__half2*>(&u0.y));
        float2 a1 = __half22float2(*reinterpret_cast<__half2*>(&u1.x));
        float2 b1 = __half22float2(*reinterpret_cast<__half2*>(&u1.y));
        acc.x += w0 * a0.x + w1 * a1.x;
        acc.y += w0 * a0.y + w1 * a1.y;
        acc.z += w0 * b0.x + w1 * b1.x;
        acc.w += w0 * b0.y + w1 * b1.y;
    }
    if (e < e1) {
        int s0 = srcg[e];
        float w0 = wg[e];
        uint2 u0 = *((const uint2*)(x + (size_t)s0 * HID) + lane);
        float2 a0 = __half22float2(*reinterpret_cast<__half2*>(&u0.x));
        float2 b0 = __half22float2(*reinterpret_cast<__half2*>(&u0.y));
        acc.x += w0 * a0.x;
        acc.y += w0 * a0.y;
        acc.z += w0 * b0.x;
        acc.w += w0 * b0.y;
    }
    float invd = 1.f / fmaxf((float)(e1 - e0), 1.f);
    acc.x *= invd; acc.y *= invd; acc.z *= invd; acc.w *= invd;

    uint2 o;
    o.x = pack_h2(__float2half(acc.x), __float2half(acc.y));
    o.y = pack_h2(__float2half(acc.z), __float2half(acc.w));
    *((uint2*)(a16 + (size_t)row * HID) + lane) = o;
}

// ---------------------------------------------------------------------------
// Host launch
// ---------------------------------------------------------------------------
extern "C" void kernel_launch(void* const* d_in, const int* in_sizes, int n_in,
                              void* d_out, int out_size)
{
    (void)in_sizes; (void)n_in; (void)out_size;

    static const int rowOffR[8] = {0, 100000, 300000, 350000, 550000, 650000, 700000, 702000};
    static const int relForDst[4][3] = { {1, 3, -1}, {0, 4, 7}, {6, -1, -1}, {2, 5, -1} };
    static const int nRelForDst[4]   = { 2, 3, 1, 2 };
    static const int    nodeN[4]   = {NU, NP, NC, NQ};
    static const size_t nodeOff[4] = {0, NU, NU + NP, NU + NP + NC};

    cudaFuncSetAttribute(gemm_mma<2,0>, cudaFuncAttributeMaxDynamicSharedMemorySize, SMEM_BYTES);
    cudaFuncSetAttribute(gemm_mma<3,0>, cudaFuncAttributeMaxDynamicSharedMemorySize, SMEM_BYTES);
    cudaFuncSetAttribute(gemm_mma<4,0>, cudaFuncAttributeMaxDynamicSharedMemorySize, SMEM_BYTES);
    cudaFuncSetAttribute(gemm_mma<2,1>, cudaFuncAttributeMaxDynamicSharedMemorySize, SMEM_BYTES);
    cudaFuncSetAttribute(gemm_mma<3,1>, cudaFuncAttributeMaxDynamicSharedMemorySize, SMEM_BYTES);
    cudaFuncSetAttribute(gemm_mma<4,1>, cudaFuncAttributeMaxDynamicSharedMemorySize, SMEM_BYTES);

    float *wsum, *bsum, *wg;
    __half *x16, *h16, *a16, *wh, *wl;
    int *cnt, *rowptr, *cursor, *srcg, *bsums;
    cudaGetSymbolAddress((void**)&x16,    g_x16);
    cudaGetSymbolAddress((void**)&h16,    g_h16);
    cudaGetSymbolAddress((void**)&a16,    g_a16);
    cudaGetSymbolAddress((void**)&cnt,    g_cnt);
    cudaGetSymbolAddress((void**)&rowptr, g_rowptr);
    cudaGetSymbolAddress((void**)&cursor, g_cursor);
    cudaGetSymbolAddress((void**)&srcg,   g_srcg);
    cudaGetSymbolAddress((void**)&wg,     g_wg);
    cudaGetSymbolAddress((void**)&bsums,  g_bsums);
    cudaGetSymbolAddress((void**)&wsum,   g_wsum);
    cudaGetSymbolAddress((void**)&bsum,   g_bsum);
    cudaGetSymbolAddress((void**)&wh,     g_wh);
    cudaGetSymbolAddress((void**)&wl,     g_wl);

    const float* xu = (const float*)d_in[0];
    const float* xp = (const float*)d_in[1];
    const float* xc = (const float*)d_in[2];
    const float* xq = (const float*)d_in[3];
    const float* W1l = (const float*)d_in[4];
    const float* b1  = (const float*)d_in[5];
    const float* W1r = (const float*)d_in[6];
    const float* W2l = (const float*)d_in[7];
    const float* b2  = (const float*)d_in[8];
    const float* W2r = (const float*)d_in[9];
    const int* eb  = (const int*)d_in[18];
    const int* es  = (const int*)d_in[19];
    const int* em  = (const int*)d_in[20];
    const int* ein = (const int*)d_in[21];
    float* out = (float*)d_out;

    cudaStream_t st = 0;
    const int NSCAN = (NROWS + 4095) / 4096;

    // ---- CSR build (layer-invariant) ----
    cudaMemsetAsync(cnt, 0, NROWS * sizeof(int), st);
    csr_count<<<(ETOT + 255) / 256, 256, 0, st>>>(eb, es, em, ein, cnt);
    scan1_kernel<<<NSCAN, 256, 0, st>>>(cnt, rowptr, bsums, NROWS);
    scan2_kernel<<<1, 32, 0, st>>>(bsums, NSCAN);
    scan3_kernel<<<NSCAN, 256, 0, st>>>(rowptr, bsums, cursor, NROWS);
    csr_fill<<<(ETOT + 255) / 256, 256, 0, st>>>(
        eb, es, em, ein,
        (const float*)d_in[10], (const float*)d_in[11], (const float*)d_in[12],
        (const float*)d_in[13], (const float*)d_in[14], (const float*)d_in[15],
        (const float*)d_in[16], (const float*)d_in[17],
        cursor, srcg, wg);

    // ---- weights + x16 ----
    wsum_kernel<<<(2 * 4 * HID * HID + 255) / 256, 256, 0, st>>>(W1l, b1, W2l, b2, wsum, bsum);
    wsplit_kernel<<<(NWCHUNK * HID * HID + 255) / 256, 256, 0, st>>>(wsum, W1r, W2r, wh, wl);
    xhalf_kernel<<<(NTOT * 16 + 255) / 256, 256, 0, st>>>(xu, xp, xc, xq, x16);

    // ---- two layers ----
    for (int layer = 0; layer < 2; layer++) {
        const __half* src = layer ? h16 : x16;
        gather_kernel<<<(NROWS * 32 + 255) / 256, 256, 0, st>>>(
            src, rowptr, srcg, wg, a16);

        for (int d = 0; d < 4; d++) {
            const __half *Ap[3]  = {nullptr, nullptr, nullptr};
            const __half *Whp[4] = {nullptr, nullptr, nullptr, nullptr};
            const __half *Wlp[4] = {nullptr, nullptr, nullptr, nullptr};
            Whp[0] = wh + (size_t)(layer * 4 + d) * HID * HID;
            Wlp[0] = wl + (size_t)(layer * 4 + d) * HID * HID;
            for (int q = 0; q < nRelForDst[d]; q++) {
                int t = relForDst[d][q];
                Ap[q] = a16 + (size_t)rowOffR[t] * HID;
                Whp[q + 1] = wh + (size_t)(8 + layer * 8 + t) * HID * HID;
                Wlp[q + 1] = wl + (size_t)(8 + layer * 8 + t) * HID * HID;
            }
            GemmArgs p;
            p.A0 = src + nodeOff[d] * HID;
            p.A1 = Ap[0]; p.A2 = Ap[1]; p.A3 = Ap[2];
            p.W0h = Whp[0]; p.W0l = Wlp[0];
            p.W1h = Whp[1]; p.W1l = Wlp[1];
            p.W2h = Whp[2]; p.W2l = Wlp[2];
            p.W3h = Whp[3]; p.W3l = Wlp[3];
            int nch = 1 + nRelForDst[d];
            float* C32 = layer ? (out + nodeOff[d] * HID) : nullptr;
            __half* C16 = layer ? nullptr : (h16 + nodeOff[d] * HID);
            const float* bs = bsum + (layer * 4 + d) * HID;
            int grid = (nodeN[d] + 127) / 128;
            if (layer == 0) {
                if (nch == 2)      gemm_mma<2,1><<<grid, 256, SMEM_BYTES, st>>>(p, bs, C32, C16, nodeN[d]);
                else if (nch == 3) gemm_mma<3,1><<<grid, 256, SMEM_BYTES, st>>>(p, bs, C32, C16, nodeN[d]);
                else               gemm_mma<4,1><<<grid, 256, SMEM_BYTES, st>>>(p, bs, C32, C16, nodeN[d]);
            } else {
                if (nch == 2)      gemm_mma<2,0><<<grid, 256, SMEM_BYTES, st>>>(p, bs, C32, C16, nodeN[d]);
                else if (nch == 3) gemm_mma<3,0><<<grid, 256, SMEM_BYTES, st>>>(p, bs, C32, C16, nodeN[d]);
                else               gemm_mma<4,0><<<grid, 256, SMEM_BYTES, st>>>(p, bs, C32, C16, nodeN[d]);
            }
        }
    }
}